// round 1
// baseline (speedup 1.0000x reference)
#include <cuda_runtime.h>
#include <cuda_bf16.h>
#include <float.h>

// Problem constants
#define BATCH 16
#define CH    256      // embedding dim D
#define HH    32
#define WW    32
#define NTOK  (BATCH*HH*WW)        // 16384 tokens
#define KCODE 8192                  // codebook size
#define QUANT_ELEMS (BATCH*CH*HH*WW)  // 4194304
#define LOSS_OFF  QUANT_ELEMS
#define IDX_OFF   (QUANT_ELEMS + 1)

// Scratch (allocation-free: __device__ globals)
__device__ float  d_enorm[KCODE];
__device__ int    d_idx[NTOK];
__device__ double d_loss_acc;

// ---------------------------------------------------------------------------
// Kernel A: ||e_k||^2 per code + zero the loss accumulator.
// One warp per code. grid = 1024 blocks x 256 threads (8 codes/block).
// ---------------------------------------------------------------------------
__global__ void prep_kernel(const float* __restrict__ E) {
    if (blockIdx.x == 0 && threadIdx.x == 0) d_loss_acc = 0.0;
    int warp = (blockIdx.x * blockDim.x + threadIdx.x) >> 5;
    int lane = threadIdx.x & 31;
    if (warp < KCODE) {
        const float* row = E + (size_t)warp * CH;
        float s = 0.f;
        #pragma unroll
        for (int d = lane; d < CH; d += 32) {
            float v = row[d];
            s = fmaf(v, v, s);
        }
        #pragma unroll
        for (int off = 16; off > 0; off >>= 1)
            s += __shfl_xor_sync(0xFFFFFFFFu, s, off);
        if (lane == 0) d_enorm[warp] = s;
    }
}

// ---------------------------------------------------------------------------
// Kernel B: fused fp32 GEMM + argmin.
// score(n,k) = ||e_k||^2 - 2 * <x_n, e_k>   (drop ||x_n||^2, constant per row)
// Tile: 128 tokens x 128 codes x 16 dims; 256 threads, 8x8 micro-tile.
// Block row-tile loops over all 64 code tiles keeping a running per-row argmin.
// Token layout: hidden is [B,C,H,W]; token n=(b, r=h*32+w); element (n,c) at
// X[b*262144 + c*1024 + r] -> 128 consecutive tokens are contiguous (coalesced).
// ---------------------------------------------------------------------------
#define TM 128
#define TN 128
#define TK 16
#define BPAD 132   // padded B-tile row stride (floats): keeps LDS.128 alignment

__global__ __launch_bounds__(256, 2)
void vq_argmin_kernel(const float* __restrict__ X, const float* __restrict__ E) {
    __shared__ float As[TK][TM];     // [dim][token]
    __shared__ float Bs[TK][BPAD];   // [dim][code], padded
    __shared__ float en[TN];
    __shared__ float redv[TM][16];
    __shared__ int   redi[TM][16];

    const int tid = threadIdx.x;
    const int tx = tid & 15;          // code group (8 cols)
    const int ty = tid >> 4;          // token group (8 rows)
    const int n0 = blockIdx.x * TM;   // token base (always within one batch b)
    const int b  = n0 >> 10;
    const int r0 = n0 & 1023;
    const float* Xb = X + (size_t)b * (CH * HH * WW) + r0;

    float rmin[8];
    int   ridx[8];
    #pragma unroll
    for (int i = 0; i < 8; i++) { rmin[i] = FLT_MAX; ridx[i] = 0; }

    for (int ct = 0; ct < KCODE / TN; ct++) {
        float acc[8][8];
        #pragma unroll
        for (int i = 0; i < 8; i++)
            #pragma unroll
            for (int j = 0; j < 8; j++) acc[i][j] = 0.f;

        for (int kc = 0; kc < CH / TK; kc++) {
            __syncthreads();   // protect smem reuse from previous iteration
            // Load A chunk: 16 dims x 128 tokens (coalesced along tokens)
            #pragma unroll
            for (int l = 0; l < 8; l++) {
                int i = tid + l * 256;
                int c = i >> 7, m = i & 127;
                As[c][m] = Xb[(size_t)(kc * TK + c) * 1024 + m];
            }
            // Load B chunk: 128 codes x 16 dims, transposed into [dim][code]
            #pragma unroll
            for (int l = 0; l < 8; l++) {
                int i = tid + l * 256;
                int code = i >> 4, d = i & 15;
                Bs[d][code] = E[(size_t)(ct * TN + code) * CH + kc * TK + d];
            }
            if (kc == 0 && tid < TN) en[tid] = d_enorm[ct * TN + tid];
            __syncthreads();

            #pragma unroll
            for (int k = 0; k < TK; k++) {
                float a[8], bb[8];
                #pragma unroll
                for (int i = 0; i < 8; i++) a[i]  = As[k][ty * 8 + i];
                #pragma unroll
                for (int j = 0; j < 8; j++) bb[j] = Bs[k][tx * 8 + j];
                #pragma unroll
                for (int i = 0; i < 8; i++)
                    #pragma unroll
                    for (int j = 0; j < 8; j++)
                        acc[i][j] = fmaf(a[i], bb[j], acc[i][j]);
            }
        }

        // Scores + running argmin (strict < keeps lowest index on ties,
        // since we scan columns in increasing global index order per thread)
        #pragma unroll
        for (int j = 0; j < 8; j++) {
            float e = en[tx * 8 + j];
            int col = ct * TN + tx * 8 + j;
            #pragma unroll
            for (int i = 0; i < 8; i++) {
                float s = fmaf(-2.f, acc[i][j], e);
                if (s < rmin[i]) { rmin[i] = s; ridx[i] = col; }
            }
        }
    }

    // Cross-thread reduction: 16 tx-lanes per token row, tie-break lowest idx
    __syncthreads();
    #pragma unroll
    for (int i = 0; i < 8; i++) {
        redv[ty * 8 + i][tx] = rmin[i];
        redi[ty * 8 + i][tx] = ridx[i];
    }
    __syncthreads();
    if (tid < TM) {
        float bv = redv[tid][0];
        int   bi = redi[tid][0];
        #pragma unroll
        for (int t = 1; t < 16; t++) {
            float v = redv[tid][t];
            int  ix = redi[tid][t];
            if (v < bv || (v == bv && ix < bi)) { bv = v; bi = ix; }
        }
        d_idx[n0 + tid] = bi;
    }
}

// ---------------------------------------------------------------------------
// Kernel C: gather codebook rows -> quant_out (in [B,C,H,W] layout), write
// min_idx region (as float), accumulate sum((q - x)^2) into d_loss_acc.
// grid = 16384 blocks x 256 threads, one thread per output element.
// ---------------------------------------------------------------------------
__global__ void gather_loss_kernel(const float* __restrict__ X,
                                   const float* __restrict__ E,
                                   float* __restrict__ out) {
    __shared__ float sdata[256];
    unsigned i = blockIdx.x * 256u + threadIdx.x;   // linear over [B,C,H,W]
    int w  = i & 31;
    int h  = (i >> 5) & 31;
    int c  = (i >> 10) & 255;
    int b  = i >> 18;
    int n  = b * 1024 + h * 32 + w;
    int k  = d_idx[n];

    float q = E[(size_t)k * CH + c];
    float x = X[i];
    out[i] = q;                         // quant_out (straight-through == quant)
    if (c == 0) out[IDX_OFF + n] = (float)k;

    float d = q - x;
    sdata[threadIdx.x] = d * d;
    __syncthreads();
    #pragma unroll
    for (int s = 128; s > 0; s >>= 1) {
        if (threadIdx.x < s) sdata[threadIdx.x] += sdata[threadIdx.x + s];
        __syncthreads();
    }
    if (threadIdx.x == 0) atomicAdd(&d_loss_acc, (double)sdata[0]);
}

// Kernel D: finalize loss = (1 + BETA) * mean
__global__ void finalize_kernel(float* __restrict__ out) {
    out[LOSS_OFF] = (float)(d_loss_acc * 1.25 / (double)QUANT_ELEMS);
}

// ---------------------------------------------------------------------------
extern "C" void kernel_launch(void* const* d_in, const int* in_sizes, int n_in,
                              void* d_out, int out_size) {
    const float* X = (const float*)d_in[0];  // hidden_state [16,256,32,32]
    const float* E = (const float*)d_in[1];  // emb_weight   [8192,256]
    float* out = (float*)d_out;

    prep_kernel<<<KCODE / 8, 256>>>(E);
    vq_argmin_kernel<<<NTOK / TM, 256>>>(X, E);
    gather_loss_kernel<<<QUANT_ELEMS / 256, 256>>>(X, E, out);
    finalize_kernel<<<1, 1>>>(out);
}

// round 4
// speedup vs baseline: 2.7251x; 2.7251x over previous
#include <cuda_runtime.h>
#include <cuda_bf16.h>
#include <float.h>
#include <stdint.h>

// ---------------------------------------------------------------------------
// Problem constants
// ---------------------------------------------------------------------------
#define BATCH 16
#define CH    256
#define HH    32
#define WW    32
#define NTOK  (BATCH*HH*WW)           // 16384
#define KCODE 8192
#define QUANT_ELEMS (BATCH*CH*HH*WW)  // 4194304
#define LOSS_OFF  QUANT_ELEMS
#define IDX_OFF   (QUANT_ELEMS + 1)

#define M_TILE 128
#define N_TILE 128
#define N_TILES (KCODE / N_TILE)      // 64
#define KC 64                         // dims per chunk
#define N_CHUNKS (CH / KC)            // 4
#define CHUNK_BYTES 16384             // 128 rows x 128B (one split)
#define STAGE_BYTES 32768             // hi + lo
#define TOTAL_ITERS (N_TILES * N_CHUNKS)  // 256

#define MARGIN 0.05f

// ---------------------------------------------------------------------------
// Device scratch (allocation-free)
// ---------------------------------------------------------------------------
__device__ __align__(128) uint8_t d_eblob[(size_t)TOTAL_ITERS * STAGE_BYTES]; // 8 MB
__device__ float  d_enorm[KCODE];
__device__ int    d_idx[NTOK];
__device__ int    d_fb_count;
__device__ int    d_fb_list[NTOK];
__device__ double d_loss_acc;

// ---------------------------------------------------------------------------
// Helpers
// ---------------------------------------------------------------------------
__device__ __forceinline__ uint32_t smem_u32(const void* p) {
    uint32_t a;
    asm("{ .reg .u64 t; cvta.to.shared.u64 t, %1; cvt.u32.u64 %0, t; }" : "=r"(a) : "l"(p));
    return a;
}
#define SWZ128(off) ((off) ^ (((off) >> 3) & 0x70))

__device__ __forceinline__ void ldsm4(uint32_t& r0, uint32_t& r1, uint32_t& r2, uint32_t& r3,
                                      uint32_t addr) {
    asm volatile("ldmatrix.sync.aligned.m8n8.x4.shared.b16 {%0,%1,%2,%3}, [%4];"
                 : "=r"(r0), "=r"(r1), "=r"(r2), "=r"(r3) : "r"(addr));
}

__device__ __forceinline__ void mma16816(float& d0, float& d1, float& d2, float& d3,
                                         uint32_t a0, uint32_t a1, uint32_t a2, uint32_t a3,
                                         uint32_t b0, uint32_t b1) {
    asm volatile(
        "mma.sync.aligned.m16n8k16.row.col.f32.bf16.bf16.f32 "
        "{%0,%1,%2,%3}, {%4,%5,%6,%7}, {%8,%9}, {%0,%1,%2,%3};"
        : "+f"(d0), "+f"(d1), "+f"(d2), "+f"(d3)
        : "r"(a0), "r"(a1), "r"(a2), "r"(a3), "r"(b0), "r"(b1));
}

__device__ __forceinline__ void cpasync16(uint32_t dst, const void* src) {
    asm volatile("cp.async.cg.shared.global [%0], [%1], 16;" :: "r"(dst), "l"(src));
}

// ---------------------------------------------------------------------------
// Kernel A: ||e_k||^2 per code + zero accumulators
// ---------------------------------------------------------------------------
__global__ void prep_kernel(const float* __restrict__ E) {
    if (blockIdx.x == 0 && threadIdx.x == 0) { d_loss_acc = 0.0; d_fb_count = 0; }
    int warp = (blockIdx.x * blockDim.x + threadIdx.x) >> 5;
    int lane = threadIdx.x & 31;
    if (warp < KCODE) {
        const float* row = E + (size_t)warp * CH;
        float s = 0.f;
        #pragma unroll
        for (int d = lane; d < CH; d += 32) { float v = row[d]; s = fmaf(v, v, s); }
        #pragma unroll
        for (int off = 16; off > 0; off >>= 1) s += __shfl_xor_sync(0xFFFFFFFFu, s, off);
        if (lane == 0) d_enorm[warp] = s;
    }
}

// ---------------------------------------------------------------------------
// Kernel B: split E -> bf16 hi/lo, pre-swizzled chunked blob.
// Layout: [ct(64)][kc(4)] { hi[128 rows x 128B SW128], lo[...] }
// ---------------------------------------------------------------------------
__global__ void eblob_kernel(const float* __restrict__ E) {
    int idx = blockIdx.x * 256 + threadIdx.x;
    int k  = idx >> 6;
    int d0 = (idx & 63) * 4;
    const float4 v = *(const float4*)(E + (size_t)k * CH + d0);

    __nv_bfloat16 h[4], l[4];
    float vv[4] = {v.x, v.y, v.z, v.w};
    #pragma unroll
    for (int q = 0; q < 4; q++) {
        h[q] = __float2bfloat16(vv[q]);
        l[q] = __float2bfloat16(vv[q] - __bfloat162float(h[q]));
    }
    int ct = k >> 7, row = k & 127, kc = d0 >> 6, col = d0 & 63;
    size_t chunk = ((size_t)(ct * N_CHUNKS + kc)) * STAGE_BYTES;
    uint32_t off = SWZ128((uint32_t)(row * 128 + col * 2));
    *(uint2*)(d_eblob + chunk + off)               = *(uint2*)h;
    *(uint2*)(d_eblob + chunk + CHUNK_BYTES + off) = *(uint2*)l;
}

// ---------------------------------------------------------------------------
// Kernel C: bf16x3 mma.sync GEMM + running argmax of (x.e - 0.5||e||^2).
// SMEM: A_h[4 chunks x 16KB] | A_l[4 x 16KB] | B[2 stages x 32KB] = 192KB
// Final cross-warp merge reuses the B region (dead after the main loop).
// ---------------------------------------------------------------------------
#define SM_A   0
#define SM_AL  65536
#define SM_B   131072
#define SM_TOTAL 196608

__global__ __launch_bounds__(256, 1)
void vq_mma_kernel(const float* __restrict__ X) {
    extern __shared__ char smem[];
    const uint32_t sb = smem_u32(smem);
    const int tid  = threadIdx.x;
    const int wid  = tid >> 5;
    const int lane = tid & 31;
    const int warpM = wid >> 1;      // 0..3  (32-token slab)
    const int warpN = wid & 1;       // 0..1  (64-code slab)
    const int n0 = blockIdx.x * M_TILE;
    const int b  = n0 >> 10;
    const int r0 = n0 & 1023;
    const float* Xb = X + (size_t)b * (CH * HH * WW) + r0;

    // ---- issue first B stage immediately (independent of A region) ----
    auto copy_stage = [&](int it) {
        uint32_t dst = sb + SM_B + (uint32_t)(it & 1) * STAGE_BYTES + tid * 16u;
        const uint8_t* src = d_eblob + (size_t)it * STAGE_BYTES + tid * 16;
        #pragma unroll
        for (int p = 0; p < 8; p++) cpasync16(dst + p * 4096u, src + p * 4096);
        asm volatile("cp.async.commit_group;" ::: "memory");
    };
    copy_stage(0);

    // ---- A prologue: X -> bf16 hi/lo, swizzled chunk layout ----
    #pragma unroll
    for (int l = 0; l < M_TILE * CH / 256; l++) {
        int i = tid + l * 256;
        int d = i >> 7, m = i & 127;
        float v = Xb[(size_t)d * 1024 + m];
        __nv_bfloat16 h = __float2bfloat16(v);
        __nv_bfloat16 lo = __float2bfloat16(v - __bfloat162float(h));
        int chunk = d >> 6, c = d & 63;
        uint32_t off = SWZ128((uint32_t)(m * 128 + c * 2));
        *(__nv_bfloat16*)(smem + SM_A  + chunk * CHUNK_BYTES + off) = h;
        *(__nv_bfloat16*)(smem + SM_AL + chunk * CHUNK_BYTES + off) = lo;
    }

    // per-lane ldmatrix address components (byte offsets within a chunk)
    const uint32_t a_row = (uint32_t)(warpM * 32 + (lane & 15)) * 128;
    const uint32_t a_col = (uint32_t)(lane >> 4) * 16;              // bytes
    const uint32_t b_row = (uint32_t)(warpN * 64 + (lane & 7) + ((lane >> 4) * 8)) * 128;
    const uint32_t b_col = (uint32_t)((lane >> 3) & 1) * 16;        // bytes

    // running trackers: [mt*2 + half]  (this warp's 64-code slab only)
    float tb1[4], tb2[4]; int ti1[4];
    #pragma unroll
    for (int t = 0; t < 4; t++) { tb1[t] = -FLT_MAX; tb2[t] = -FLT_MAX; ti1[t] = 0; }

    for (int ct = 0; ct < N_TILES; ct++) {
        float acc[2][8][4];
        #pragma unroll
        for (int mt = 0; mt < 2; mt++)
            #pragma unroll
            for (int nt = 0; nt < 8; nt++)
                #pragma unroll
                for (int e = 0; e < 4; e++) acc[mt][nt][e] = 0.f;

        for (int kc = 0; kc < N_CHUNKS; kc++) {
            int it = ct * N_CHUNKS + kc;
            if (it + 1 < TOTAL_ITERS) {
                copy_stage(it + 1);
                asm volatile("cp.async.wait_group 1;" ::: "memory");
            } else {
                asm volatile("cp.async.wait_group 0;" ::: "memory");
            }
            __syncthreads();

            const uint32_t ah_base = sb + SM_A  + (uint32_t)kc * CHUNK_BYTES;
            const uint32_t al_base = sb + SM_AL + (uint32_t)kc * CHUNK_BYTES;
            const uint32_t bh_base = sb + SM_B + (uint32_t)(it & 1) * STAGE_BYTES;
            const uint32_t bl_base = bh_base + CHUNK_BYTES;

            #pragma unroll
            for (int ks = 0; ks < 4; ks++) {
                const uint32_t kb = (uint32_t)ks * 32;   // bytes (16 dims)
                uint32_t ah[2][4], al[2][4];
                #pragma unroll
                for (int mt = 0; mt < 2; mt++) {
                    uint32_t o = SWZ128(a_row + (uint32_t)mt * 2048 + a_col + kb);
                    ldsm4(ah[mt][0], ah[mt][1], ah[mt][2], ah[mt][3], ah_base + o);
                    ldsm4(al[mt][0], al[mt][1], al[mt][2], al[mt][3], al_base + o);
                }
                uint32_t bh[4][4], bl[4][4];
                #pragma unroll
                for (int np = 0; np < 4; np++) {
                    uint32_t o = SWZ128(b_row + (uint32_t)np * 2048 + b_col + kb);
                    ldsm4(bh[np][0], bh[np][1], bh[np][2], bh[np][3], bh_base + o);
                    ldsm4(bl[np][0], bl[np][1], bl[np][2], bl[np][3], bl_base + o);
                }
                #pragma unroll
                for (int mt = 0; mt < 2; mt++)
                    #pragma unroll
                    for (int nt = 0; nt < 8; nt++) {
                        const int np = nt >> 1, s = (nt & 1) * 2;
                        float* d = acc[mt][nt];
                        mma16816(d[0], d[1], d[2], d[3],
                                 ah[mt][0], ah[mt][1], ah[mt][2], ah[mt][3],
                                 bh[np][s], bh[np][s + 1]);
                        mma16816(d[0], d[1], d[2], d[3],
                                 al[mt][0], al[mt][1], al[mt][2], al[mt][3],
                                 bh[np][s], bh[np][s + 1]);
                        mma16816(d[0], d[1], d[2], d[3],
                                 ah[mt][0], ah[mt][1], ah[mt][2], ah[mt][3],
                                 bl[np][s], bl[np][s + 1]);
                    }
            }
            __syncthreads();
        }

        // ---- epilogue: scores for this 128-code tile (this warp's 64 codes) ----
        const int cb = ct * N_TILE + warpN * 64;
        #pragma unroll
        for (int mt = 0; mt < 2; mt++)
            #pragma unroll
            for (int nt = 0; nt < 8; nt++) {
                int col0 = cb + nt * 8 + (lane & 3) * 2;
                float e0 = 0.5f * __ldg(d_enorm + col0);
                float e1 = 0.5f * __ldg(d_enorm + col0 + 1);
                #pragma unroll
                for (int half = 0; half < 2; half++) {
                    int t = mt * 2 + half;
                    float v0 = acc[mt][nt][half * 2 + 0] - e0;
                    float v1 = acc[mt][nt][half * 2 + 1] - e1;
                    if (v0 > tb1[t]) { tb2[t] = tb1[t]; tb1[t] = v0; ti1[t] = col0; }
                    else if (v0 > tb2[t]) tb2[t] = v0;
                    if (v1 > tb1[t]) { tb2[t] = tb1[t]; tb1[t] = v1; ti1[t] = col0 + 1; }
                    else if (v1 > tb2[t]) tb2[t] = v1;
                }
            }
    }

    // ---- quad reduction within warp (4 lanes share a token row) ----
    #pragma unroll
    for (int t = 0; t < 4; t++) {
        #pragma unroll
        for (int m = 1; m <= 2; m <<= 1) {
            float ob1 = __shfl_xor_sync(0xFFFFFFFFu, tb1[t], m);
            float ob2 = __shfl_xor_sync(0xFFFFFFFFu, tb2[t], m);
            int   oi  = __shfl_xor_sync(0xFFFFFFFFu, ti1[t], m);
            if (ob1 > tb1[t] || (ob1 == tb1[t] && oi < ti1[t])) {
                tb2[t] = fmaxf(tb1[t], ob2);
                tb1[t] = ob1; ti1[t] = oi;
            } else {
                tb2[t] = fmaxf(tb2[t], ob1);
            }
        }
    }

    // ---- cross-warpN merge: each warp only saw half the codes per tile ----
    __syncthreads();                       // B region now dead -> reuse
    float* red_b1 = (float*)(smem + SM_B);          // [2][128]
    float* red_b2 = (float*)(smem + SM_B + 1024);   // [2][128]
    int*   red_i1 = (int*)  (smem + SM_B + 2048);   // [2][128]
    #pragma unroll
    for (int t = 0; t < 4; t++) {
        if ((lane & 3) == 0) {
            int mt = t >> 1, half = t & 1;
            int tl = warpM * 32 + mt * 16 + half * 8 + (lane >> 2);
            red_b1[warpN * 128 + tl] = tb1[t];
            red_b2[warpN * 128 + tl] = tb2[t];
            red_i1[warpN * 128 + tl] = ti1[t];
        }
    }
    __syncthreads();
    if (tid < M_TILE) {
        float a1 = red_b1[tid],       a2 = red_b2[tid];
        int   ai = red_i1[tid];
        float c1 = red_b1[128 + tid], c2 = red_b2[128 + tid];
        int   ci = red_i1[128 + tid];
        float m1, m2; int mi;
        if (c1 > a1 || (c1 == a1 && ci < ai)) { m1 = c1; mi = ci; m2 = fmaxf(a1, c2); }
        else                                   { m1 = a1; mi = ai; m2 = fmaxf(c1, a2); }
        int n = n0 + tid;
        d_idx[n] = mi;
        if (2.0f * (m1 - m2) < MARGIN) {
            int p = atomicAdd(&d_fb_count, 1);
            if (p < NTOK) d_fb_list[p] = n;
        }
    }
}

// ---------------------------------------------------------------------------
// Kernel D: exact fp32 re-scan for flagged (small-gap) tokens.
// ---------------------------------------------------------------------------
__global__ __launch_bounds__(256)
void fb_kernel(const float* __restrict__ X, const float* __restrict__ E) {
    __shared__ float xs[CH];
    __shared__ float rv[256];
    __shared__ int   ri[256];
    const int tid = threadIdx.x;
    const int cnt = d_fb_count;
    for (int w = blockIdx.x; w < cnt && w < NTOK; w += gridDim.x) {
        int n = d_fb_list[w];
        int b = n >> 10, r = n & 1023;
        __syncthreads();
        xs[tid] = X[(size_t)b * (CH * HH * WW) + (size_t)tid * 1024 + r];
        __syncthreads();

        const float4* xs4 = (const float4*)xs;
        float bv = FLT_MAX; int bi = 0;
        for (int i = 0; i < KCODE / 256; i++) {
            int k = (i << 8) + tid;
            const float4* e4 = (const float4*)(E + (size_t)k * CH);
            float s0 = 0.f, s1 = 0.f, s2 = 0.f, s3 = 0.f;
            #pragma unroll 8
            for (int q = 0; q < CH / 4; q++) {
                float4 a = xs4[q]; float4 e = e4[q];
                s0 = fmaf(a.x, e.x, s0); s1 = fmaf(a.y, e.y, s1);
                s2 = fmaf(a.z, e.z, s2); s3 = fmaf(a.w, e.w, s3);
            }
            float dot = (s0 + s1) + (s2 + s3);
            float sc = fmaf(-2.f, dot, d_enorm[k]);
            if (sc < bv || (sc == bv && k < bi)) { bv = sc; bi = k; }
        }
        rv[tid] = bv; ri[tid] = bi;
        __syncthreads();
        for (int s = 128; s > 0; s >>= 1) {
            if (tid < s) {
                float ov = rv[tid + s]; int oi = ri[tid + s];
                if (ov < rv[tid] || (ov == rv[tid] && oi < ri[tid])) { rv[tid] = ov; ri[tid] = oi; }
            }
            __syncthreads();
        }
        if (tid == 0) d_idx[n] = ri[0];
    }
}

// ---------------------------------------------------------------------------
// Kernel E: gather -> quant_out, idx, loss accumulation
// ---------------------------------------------------------------------------
__global__ void gather_loss_kernel(const float* __restrict__ X,
                                   const float* __restrict__ E,
                                   float* __restrict__ out) {
    __shared__ float sdata[256];
    unsigned i = blockIdx.x * 256u + threadIdx.x;
    int w  = i & 31;
    int h  = (i >> 5) & 31;
    int c  = (i >> 10) & 255;
    int bb = i >> 18;
    int n  = bb * 1024 + h * 32 + w;
    int k  = d_idx[n];

    float q = E[(size_t)k * CH + c];
    float x = X[i];
    out[i] = q;
    if (c == 0) out[IDX_OFF + n] = (float)k;

    float d = q - x;
    sdata[threadIdx.x] = d * d;
    __syncthreads();
    #pragma unroll
    for (int s = 128; s > 0; s >>= 1) {
        if (threadIdx.x < s) sdata[threadIdx.x] += sdata[threadIdx.x + s];
        __syncthreads();
    }
    if (threadIdx.x == 0) atomicAdd(&d_loss_acc, (double)sdata[0]);
}

__global__ void finalize_kernel(float* __restrict__ out) {
    out[LOSS_OFF] = (float)(d_loss_acc * 1.25 / (double)QUANT_ELEMS);
}

// ---------------------------------------------------------------------------
extern "C" void kernel_launch(void* const* d_in, const int* in_sizes, int n_in,
                              void* d_out, int out_size) {
    const float* X = (const float*)d_in[0];
    const float* E = (const float*)d_in[1];
    float* out = (float*)d_out;

    cudaFuncSetAttribute(vq_mma_kernel, cudaFuncAttributeMaxDynamicSharedMemorySize, SM_TOTAL);

    prep_kernel<<<KCODE / 8, 256>>>(E);
    eblob_kernel<<<KCODE * CH / 4 / 256, 256>>>(E);
    vq_mma_kernel<<<NTOK / M_TILE, 256, SM_TOTAL>>>(X);
    fb_kernel<<<512, 256>>>(X, E);
    gather_loss_kernel<<<QUANT_ELEMS / 256, 256>>>(X, E, out);
    finalize_kernel<<<1, 1>>>(out);
}

// round 5
// speedup vs baseline: 3.5317x; 1.2960x over previous
#include <cuda_runtime.h>
#include <cuda_bf16.h>
#include <float.h>
#include <stdint.h>

// ---------------------------------------------------------------------------
// Problem constants
// ---------------------------------------------------------------------------
#define BATCH 16
#define CH    256
#define HH    32
#define WW    32
#define NTOK  (BATCH*HH*WW)           // 16384
#define KCODE 8192
#define QUANT_ELEMS (BATCH*CH*HH*WW)  // 4194304
#define LOSS_OFF  QUANT_ELEMS
#define IDX_OFF   (QUANT_ELEMS + 1)

#define M_TILE 128
#define N_TILE 128
#define N_TILES (KCODE / N_TILE)      // 64
#define KC 64                         // dims per chunk
#define N_CHUNKS (CH / KC)            // 4
#define CHUNK_BYTES 16384             // 128 rows x 128B (one split)
#define STAGE_BYTES 32768             // hi + lo
#define TOTAL_ITERS (N_TILES * N_CHUNKS)  // 256

#define MARGIN 0.01f

#define FB_SEGS  32
#define FB_CODES (KCODE / FB_SEGS)    // 256

// ---------------------------------------------------------------------------
// Device scratch (allocation-free)
// ---------------------------------------------------------------------------
__device__ __align__(128) uint8_t d_eblob[(size_t)TOTAL_ITERS * STAGE_BYTES]; // 8 MB
__device__ float  d_enorm[KCODE];
__device__ int    d_idx[NTOK];
__device__ int    d_fb_count;
__device__ int    d_fb_list[NTOK];
__device__ unsigned long long d_fb_best[NTOK];
__device__ double d_loss_acc;

// ---------------------------------------------------------------------------
// Helpers
// ---------------------------------------------------------------------------
__device__ __forceinline__ uint32_t smem_u32(const void* p) {
    uint32_t a;
    asm("{ .reg .u64 t; cvta.to.shared.u64 t, %1; cvt.u32.u64 %0, t; }" : "=r"(a) : "l"(p));
    return a;
}
#define SWZ128(off) ((off) ^ (((off) >> 3) & 0x70))

__device__ __forceinline__ void ldsm4(uint32_t& r0, uint32_t& r1, uint32_t& r2, uint32_t& r3,
                                      uint32_t addr) {
    asm volatile("ldmatrix.sync.aligned.m8n8.x4.shared.b16 {%0,%1,%2,%3}, [%4];"
                 : "=r"(r0), "=r"(r1), "=r"(r2), "=r"(r3) : "r"(addr));
}

__device__ __forceinline__ void mma16816(float& d0, float& d1, float& d2, float& d3,
                                         uint32_t a0, uint32_t a1, uint32_t a2, uint32_t a3,
                                         uint32_t b0, uint32_t b1) {
    asm volatile(
        "mma.sync.aligned.m16n8k16.row.col.f32.bf16.bf16.f32 "
        "{%0,%1,%2,%3}, {%4,%5,%6,%7}, {%8,%9}, {%0,%1,%2,%3};"
        : "+f"(d0), "+f"(d1), "+f"(d2), "+f"(d3)
        : "r"(a0), "r"(a1), "r"(a2), "r"(a3), "r"(b0), "r"(b1));
}

__device__ __forceinline__ void cpasync16(uint32_t dst, const void* src) {
    asm volatile("cp.async.cg.shared.global [%0], [%1], 16;" :: "r"(dst), "l"(src));
}

// order-preserving float->uint map: a < b  <=>  ord(a) < ord(b)
__device__ __forceinline__ unsigned ord_f32(float f) {
    unsigned u = __float_as_uint(f);
    return (u & 0x80000000u) ? ~u : (u | 0x80000000u);
}

// ---------------------------------------------------------------------------
// Kernel A: ||e_k||^2 per code + zero accumulators
// ---------------------------------------------------------------------------
__global__ void prep_kernel(const float* __restrict__ E) {
    if (blockIdx.x == 0 && threadIdx.x == 0) { d_loss_acc = 0.0; d_fb_count = 0; }
    int warp = (blockIdx.x * blockDim.x + threadIdx.x) >> 5;
    int lane = threadIdx.x & 31;
    if (warp < KCODE) {
        const float* row = E + (size_t)warp * CH;
        float s = 0.f;
        #pragma unroll
        for (int d = lane; d < CH; d += 32) { float v = row[d]; s = fmaf(v, v, s); }
        #pragma unroll
        for (int off = 16; off > 0; off >>= 1) s += __shfl_xor_sync(0xFFFFFFFFu, s, off);
        if (lane == 0) d_enorm[warp] = s;
    }
}

// ---------------------------------------------------------------------------
// Kernel B: split E -> bf16 hi/lo, pre-swizzled chunked blob.
// Layout: [ct(64)][kc(4)] { hi[128 rows x 128B SW128], lo[...] }
// ---------------------------------------------------------------------------
__global__ void eblob_kernel(const float* __restrict__ E) {
    int idx = blockIdx.x * 256 + threadIdx.x;
    int k  = idx >> 6;
    int d0 = (idx & 63) * 4;
    const float4 v = *(const float4*)(E + (size_t)k * CH + d0);

    __nv_bfloat16 h[4], l[4];
    float vv[4] = {v.x, v.y, v.z, v.w};
    #pragma unroll
    for (int q = 0; q < 4; q++) {
        h[q] = __float2bfloat16(vv[q]);
        l[q] = __float2bfloat16(vv[q] - __bfloat162float(h[q]));
    }
    int ct = k >> 7, row = k & 127, kc = d0 >> 6, col = d0 & 63;
    size_t chunk = ((size_t)(ct * N_CHUNKS + kc)) * STAGE_BYTES;
    uint32_t off = SWZ128((uint32_t)(row * 128 + col * 2));
    *(uint2*)(d_eblob + chunk + off)               = *(uint2*)h;
    *(uint2*)(d_eblob + chunk + CHUNK_BYTES + off) = *(uint2*)l;
}

// ---------------------------------------------------------------------------
// Kernel C: bf16x3 mma.sync GEMM + running argmax of (x.e - 0.5||e||^2).
// SMEM: A_h[4 chunks x 16KB] | A_l[4 x 16KB] | B[2 stages x 32KB] = 192KB
// Final cross-warp merge reuses the B region (dead after the main loop).
// ---------------------------------------------------------------------------
#define SM_A   0
#define SM_AL  65536
#define SM_B   131072
#define SM_TOTAL 196608

__global__ __launch_bounds__(256, 1)
void vq_mma_kernel(const float* __restrict__ X) {
    extern __shared__ char smem[];
    const uint32_t sb = smem_u32(smem);
    const int tid  = threadIdx.x;
    const int wid  = tid >> 5;
    const int lane = tid & 31;
    const int warpM = wid >> 1;      // 0..3  (32-token slab)
    const int warpN = wid & 1;       // 0..1  (64-code slab)
    const int n0 = blockIdx.x * M_TILE;
    const int b  = n0 >> 10;
    const int r0 = n0 & 1023;
    const float* Xb = X + (size_t)b * (CH * HH * WW) + r0;

    // ---- issue first B stage immediately (independent of A region) ----
    auto copy_stage = [&](int it) {
        uint32_t dst = sb + SM_B + (uint32_t)(it & 1) * STAGE_BYTES + tid * 16u;
        const uint8_t* src = d_eblob + (size_t)it * STAGE_BYTES + tid * 16;
        #pragma unroll
        for (int p = 0; p < 8; p++) cpasync16(dst + p * 4096u, src + p * 4096);
        asm volatile("cp.async.commit_group;" ::: "memory");
    };
    copy_stage(0);

    // ---- A prologue: X -> bf16 hi/lo, swizzled chunk layout ----
    #pragma unroll
    for (int l = 0; l < M_TILE * CH / 256; l++) {
        int i = tid + l * 256;
        int d = i >> 7, m = i & 127;
        float v = Xb[(size_t)d * 1024 + m];
        __nv_bfloat16 h = __float2bfloat16(v);
        __nv_bfloat16 lo = __float2bfloat16(v - __bfloat162float(h));
        int chunk = d >> 6, c = d & 63;
        uint32_t off = SWZ128((uint32_t)(m * 128 + c * 2));
        *(__nv_bfloat16*)(smem + SM_A  + chunk * CHUNK_BYTES + off) = h;
        *(__nv_bfloat16*)(smem + SM_AL + chunk * CHUNK_BYTES + off) = lo;
    }

    // per-lane ldmatrix address components (byte offsets within a chunk)
    const uint32_t a_row = (uint32_t)(warpM * 32 + (lane & 15)) * 128;
    const uint32_t a_col = (uint32_t)(lane >> 4) * 16;              // bytes
    const uint32_t b_row = (uint32_t)(warpN * 64 + (lane & 7) + ((lane >> 4) * 8)) * 128;
    const uint32_t b_col = (uint32_t)((lane >> 3) & 1) * 16;        // bytes

    // running trackers: [mt*2 + half]  (this warp's 64-code slab only)
    float tb1[4], tb2[4]; int ti1[4];
    #pragma unroll
    for (int t = 0; t < 4; t++) { tb1[t] = -FLT_MAX; tb2[t] = -FLT_MAX; ti1[t] = 0; }

    for (int ct = 0; ct < N_TILES; ct++) {
        float acc[2][8][4];
        #pragma unroll
        for (int mt = 0; mt < 2; mt++)
            #pragma unroll
            for (int nt = 0; nt < 8; nt++)
                #pragma unroll
                for (int e = 0; e < 4; e++) acc[mt][nt][e] = 0.f;

        for (int kc = 0; kc < N_CHUNKS; kc++) {
            int it = ct * N_CHUNKS + kc;
            if (it + 1 < TOTAL_ITERS) {
                copy_stage(it + 1);
                asm volatile("cp.async.wait_group 1;" ::: "memory");
            } else {
                asm volatile("cp.async.wait_group 0;" ::: "memory");
            }
            __syncthreads();

            const uint32_t ah_base = sb + SM_A  + (uint32_t)kc * CHUNK_BYTES;
            const uint32_t al_base = sb + SM_AL + (uint32_t)kc * CHUNK_BYTES;
            const uint32_t bh_base = sb + SM_B + (uint32_t)(it & 1) * STAGE_BYTES;
            const uint32_t bl_base = bh_base + CHUNK_BYTES;

            #pragma unroll
            for (int ks = 0; ks < 4; ks++) {
                const uint32_t kb = (uint32_t)ks * 32;   // bytes (16 dims)
                uint32_t ah[2][4], al[2][4];
                #pragma unroll
                for (int mt = 0; mt < 2; mt++) {
                    uint32_t o = SWZ128(a_row + (uint32_t)mt * 2048 + a_col + kb);
                    ldsm4(ah[mt][0], ah[mt][1], ah[mt][2], ah[mt][3], ah_base + o);
                    ldsm4(al[mt][0], al[mt][1], al[mt][2], al[mt][3], al_base + o);
                }
                uint32_t bh[4][4], bl[4][4];
                #pragma unroll
                for (int np = 0; np < 4; np++) {
                    uint32_t o = SWZ128(b_row + (uint32_t)np * 2048 + b_col + kb);
                    ldsm4(bh[np][0], bh[np][1], bh[np][2], bh[np][3], bh_base + o);
                    ldsm4(bl[np][0], bl[np][1], bl[np][2], bl[np][3], bl_base + o);
                }
                #pragma unroll
                for (int mt = 0; mt < 2; mt++)
                    #pragma unroll
                    for (int nt = 0; nt < 8; nt++) {
                        const int np = nt >> 1, s = (nt & 1) * 2;
                        float* d = acc[mt][nt];
                        mma16816(d[0], d[1], d[2], d[3],
                                 ah[mt][0], ah[mt][1], ah[mt][2], ah[mt][3],
                                 bh[np][s], bh[np][s + 1]);
                        mma16816(d[0], d[1], d[2], d[3],
                                 al[mt][0], al[mt][1], al[mt][2], al[mt][3],
                                 bh[np][s], bh[np][s + 1]);
                        mma16816(d[0], d[1], d[2], d[3],
                                 ah[mt][0], ah[mt][1], ah[mt][2], ah[mt][3],
                                 bl[np][s], bl[np][s + 1]);
                    }
            }
            __syncthreads();
        }

        // ---- epilogue: scores for this 128-code tile (this warp's 64 codes) ----
        const int cb = ct * N_TILE + warpN * 64;
        #pragma unroll
        for (int mt = 0; mt < 2; mt++)
            #pragma unroll
            for (int nt = 0; nt < 8; nt++) {
                int col0 = cb + nt * 8 + (lane & 3) * 2;
                float e0 = 0.5f * __ldg(d_enorm + col0);
                float e1 = 0.5f * __ldg(d_enorm + col0 + 1);
                #pragma unroll
                for (int half = 0; half < 2; half++) {
                    int t = mt * 2 + half;
                    float v0 = acc[mt][nt][half * 2 + 0] - e0;
                    float v1 = acc[mt][nt][half * 2 + 1] - e1;
                    if (v0 > tb1[t]) { tb2[t] = tb1[t]; tb1[t] = v0; ti1[t] = col0; }
                    else if (v0 > tb2[t]) tb2[t] = v0;
                    if (v1 > tb1[t]) { tb2[t] = tb1[t]; tb1[t] = v1; ti1[t] = col0 + 1; }
                    else if (v1 > tb2[t]) tb2[t] = v1;
                }
            }
    }

    // ---- quad reduction within warp (4 lanes share a token row) ----
    #pragma unroll
    for (int t = 0; t < 4; t++) {
        #pragma unroll
        for (int m = 1; m <= 2; m <<= 1) {
            float ob1 = __shfl_xor_sync(0xFFFFFFFFu, tb1[t], m);
            float ob2 = __shfl_xor_sync(0xFFFFFFFFu, tb2[t], m);
            int   oi  = __shfl_xor_sync(0xFFFFFFFFu, ti1[t], m);
            if (ob1 > tb1[t] || (ob1 == tb1[t] && oi < ti1[t])) {
                tb2[t] = fmaxf(tb1[t], ob2);
                tb1[t] = ob1; ti1[t] = oi;
            } else {
                tb2[t] = fmaxf(tb2[t], ob1);
            }
        }
    }

    // ---- cross-warpN merge: each warp only saw half the codes per tile ----
    __syncthreads();                       // B region now dead -> reuse
    float* red_b1 = (float*)(smem + SM_B);          // [2][128]
    float* red_b2 = (float*)(smem + SM_B + 1024);   // [2][128]
    int*   red_i1 = (int*)  (smem + SM_B + 2048);   // [2][128]
    #pragma unroll
    for (int t = 0; t < 4; t++) {
        if ((lane & 3) == 0) {
            int mt = t >> 1, half = t & 1;
            int tl = warpM * 32 + mt * 16 + half * 8 + (lane >> 2);
            red_b1[warpN * 128 + tl] = tb1[t];
            red_b2[warpN * 128 + tl] = tb2[t];
            red_i1[warpN * 128 + tl] = ti1[t];
        }
    }
    __syncthreads();
    if (tid < M_TILE) {
        float a1 = red_b1[tid],       a2 = red_b2[tid];
        int   ai = red_i1[tid];
        float c1 = red_b1[128 + tid], c2 = red_b2[128 + tid];
        int   ci = red_i1[128 + tid];
        float m1, m2; int mi;
        if (c1 > a1 || (c1 == a1 && ci < ai)) { m1 = c1; mi = ci; m2 = fmaxf(a1, c2); }
        else                                   { m1 = a1; mi = ai; m2 = fmaxf(c1, a2); }
        int n = n0 + tid;
        d_idx[n] = mi;
        if (2.0f * (m1 - m2) < MARGIN) {
            int p = atomicAdd(&d_fb_count, 1);
            if (p < NTOK) {
                d_fb_list[p] = n;
                d_fb_best[n] = 0xFFFFFFFFFFFFFFFFull;
            }
        }
    }
}

// ---------------------------------------------------------------------------
// Kernel D: exact fp32 re-scan for flagged tokens, split-K parallel.
// Work item = (token, 256-code segment). 1 code/thread; block-min then one
// atomicMin on an order-encoded (score, idx) key => exact strict-< + low-idx.
// ---------------------------------------------------------------------------
__global__ __launch_bounds__(256)
void fb_kernel(const float* __restrict__ X, const float* __restrict__ E) {
    __shared__ float xs[CH];
    __shared__ unsigned long long red[256];
    const int tid = threadIdx.x;
    int cnt = d_fb_count; if (cnt > NTOK) cnt = NTOK;
    const int total = cnt * FB_SEGS;
    for (int w = blockIdx.x; w < total; w += gridDim.x) {
        const int n   = d_fb_list[w >> 5];
        const int seg = w & (FB_SEGS - 1);
        const int b = n >> 10, r = n & 1023;
        __syncthreads();
        xs[tid] = X[(size_t)b * (CH * HH * WW) + (size_t)tid * 1024 + r];
        __syncthreads();

        const int k = seg * FB_CODES + tid;
        const float4* xs4 = (const float4*)xs;
        const float4* e4  = (const float4*)(E + (size_t)k * CH);
        float s0 = 0.f, s1 = 0.f, s2 = 0.f, s3 = 0.f;
        #pragma unroll 8
        for (int q = 0; q < CH / 4; q++) {
            float4 a = xs4[q]; float4 e = e4[q];
            s0 = fmaf(a.x, e.x, s0); s1 = fmaf(a.y, e.y, s1);
            s2 = fmaf(a.z, e.z, s2); s3 = fmaf(a.w, e.w, s3);
        }
        float dot = (s0 + s1) + (s2 + s3);
        float sc = fmaf(-2.f, dot, d_enorm[k]);
        red[tid] = ((unsigned long long)ord_f32(sc) << 32) | (unsigned)k;
        __syncthreads();
        #pragma unroll
        for (int s = 128; s > 0; s >>= 1) {
            if (tid < s) { unsigned long long o = red[tid + s]; if (o < red[tid]) red[tid] = o; }
            __syncthreads();
        }
        if (tid == 0) atomicMin(&d_fb_best[n], red[0]);
    }
}

__global__ void fb_finalize_kernel() {
    int w = blockIdx.x * 256 + threadIdx.x;
    int cnt = d_fb_count; if (cnt > NTOK) cnt = NTOK;
    if (w < cnt) {
        int n = d_fb_list[w];
        d_idx[n] = (int)(unsigned)(d_fb_best[n] & 0xFFFFFFFFull);
    }
}

// ---------------------------------------------------------------------------
// Kernel E: gather -> quant_out, idx, loss accumulation
// ---------------------------------------------------------------------------
__global__ void gather_loss_kernel(const float* __restrict__ X,
                                   const float* __restrict__ E,
                                   float* __restrict__ out) {
    __shared__ float sdata[256];
    unsigned i = blockIdx.x * 256u + threadIdx.x;
    int w  = i & 31;
    int h  = (i >> 5) & 31;
    int c  = (i >> 10) & 255;
    int bb = i >> 18;
    int n  = bb * 1024 + h * 32 + w;
    int k  = d_idx[n];

    float q = E[(size_t)k * CH + c];
    float x = X[i];
    out[i] = q;
    if (c == 0) out[IDX_OFF + n] = (float)k;

    float d = q - x;
    sdata[threadIdx.x] = d * d;
    __syncthreads();
    #pragma unroll
    for (int s = 128; s > 0; s >>= 1) {
        if (threadIdx.x < s) sdata[threadIdx.x] += sdata[threadIdx.x + s];
        __syncthreads();
    }
    if (threadIdx.x == 0) atomicAdd(&d_loss_acc, (double)sdata[0]);
}

__global__ void finalize_kernel(float* __restrict__ out) {
    out[LOSS_OFF] = (float)(d_loss_acc * 1.25 / (double)QUANT_ELEMS);
}

// ---------------------------------------------------------------------------
extern "C" void kernel_launch(void* const* d_in, const int* in_sizes, int n_in,
                              void* d_out, int out_size) {
    const float* X = (const float*)d_in[0];
    const float* E = (const float*)d_in[1];
    float* out = (float*)d_out;

    cudaFuncSetAttribute(vq_mma_kernel, cudaFuncAttributeMaxDynamicSharedMemorySize, SM_TOTAL);

    prep_kernel<<<KCODE / 8, 256>>>(E);
    eblob_kernel<<<KCODE * CH / 4 / 256, 256>>>(E);
    vq_mma_kernel<<<NTOK / M_TILE, 256, SM_TOTAL>>>(X);
    fb_kernel<<<2048, 256>>>(X, E);
    fb_finalize_kernel<<<NTOK / 256, 256>>>();
    gather_loss_kernel<<<QUANT_ELEMS / 256, 256>>>(X, E, out);
    finalize_kernel<<<1, 1>>>(out);
}

// round 6
// speedup vs baseline: 3.8590x; 1.0927x over previous
#include <cuda_runtime.h>
#include <cuda_fp16.h>
#include <float.h>
#include <stdint.h>

// ---------------------------------------------------------------------------
// Problem constants
// ---------------------------------------------------------------------------
#define BATCH 16
#define CH    256
#define HH    32
#define WW    32
#define NTOK  (BATCH*HH*WW)           // 16384
#define KCODE 8192
#define QUANT_ELEMS (BATCH*CH*HH*WW)  // 4194304
#define LOSS_OFF  QUANT_ELEMS
#define IDX_OFF   (QUANT_ELEMS + 1)

#define M_TILE 128
#define N_TILE 128
#define N_TILES (KCODE / N_TILE)      // 64
#define KC 64                         // dims per chunk
#define N_CHUNKS (CH / KC)            // 4
#define CHUNK_BYTES 16384             // 128 rows x 128B (one split)
#define STAGE_BYTES 32768             // hi + lo
#define TOTAL_ITERS (N_TILES * N_CHUNKS)  // 256

#define MARGIN 0.001f

#define FB_SEGS  32
#define FB_CODES (KCODE / FB_SEGS)    // 256

// ---------------------------------------------------------------------------
// Device scratch (allocation-free)
// ---------------------------------------------------------------------------
__device__ __align__(128) uint8_t d_eblob[(size_t)TOTAL_ITERS * STAGE_BYTES]; // 8 MB
__device__ float  d_enorm[KCODE];
__device__ int    d_idx[NTOK];
__device__ int    d_fb_count;
__device__ int    d_fb_list[NTOK];
__device__ unsigned long long d_fb_best[NTOK];
__device__ double d_loss_acc;

// ---------------------------------------------------------------------------
// Helpers
// ---------------------------------------------------------------------------
__device__ __forceinline__ uint32_t smem_u32(const void* p) {
    uint32_t a;
    asm("{ .reg .u64 t; cvta.to.shared.u64 t, %1; cvt.u32.u64 %0, t; }" : "=r"(a) : "l"(p));
    return a;
}
#define SWZ128(off) ((off) ^ (((off) >> 3) & 0x70))

__device__ __forceinline__ void ldsm4(uint32_t& r0, uint32_t& r1, uint32_t& r2, uint32_t& r3,
                                      uint32_t addr) {
    asm volatile("ldmatrix.sync.aligned.m8n8.x4.shared.b16 {%0,%1,%2,%3}, [%4];"
                 : "=r"(r0), "=r"(r1), "=r"(r2), "=r"(r3) : "r"(addr));
}

__device__ __forceinline__ void mma16816(float& d0, float& d1, float& d2, float& d3,
                                         uint32_t a0, uint32_t a1, uint32_t a2, uint32_t a3,
                                         uint32_t b0, uint32_t b1) {
    asm volatile(
        "mma.sync.aligned.m16n8k16.row.col.f32.f16.f16.f32 "
        "{%0,%1,%2,%3}, {%4,%5,%6,%7}, {%8,%9}, {%0,%1,%2,%3};"
        : "+f"(d0), "+f"(d1), "+f"(d2), "+f"(d3)
        : "r"(a0), "r"(a1), "r"(a2), "r"(a3), "r"(b0), "r"(b1));
}

__device__ __forceinline__ void cpasync16(uint32_t dst, const void* src) {
    asm volatile("cp.async.cg.shared.global [%0], [%1], 16;" :: "r"(dst), "l"(src));
}

// order-preserving float->uint map: a < b  <=>  ord(a) < ord(b)
__device__ __forceinline__ unsigned ord_f32(float f) {
    unsigned u = __float_as_uint(f);
    return (u & 0x80000000u) ? ~u : (u | 0x80000000u);
}

// ---------------------------------------------------------------------------
// Kernel A: ||e_k||^2 per code + zero accumulators
// ---------------------------------------------------------------------------
__global__ void prep_kernel(const float* __restrict__ E) {
    if (blockIdx.x == 0 && threadIdx.x == 0) { d_loss_acc = 0.0; d_fb_count = 0; }
    int warp = (blockIdx.x * blockDim.x + threadIdx.x) >> 5;
    int lane = threadIdx.x & 31;
    if (warp < KCODE) {
        const float* row = E + (size_t)warp * CH;
        float s = 0.f;
        #pragma unroll
        for (int d = lane; d < CH; d += 32) { float v = row[d]; s = fmaf(v, v, s); }
        #pragma unroll
        for (int off = 16; off > 0; off >>= 1) s += __shfl_xor_sync(0xFFFFFFFFu, s, off);
        if (lane == 0) d_enorm[warp] = s;
    }
}

// ---------------------------------------------------------------------------
// Kernel B: split E -> fp16 hi/lo, pre-swizzled chunked blob.
// Layout: [ct(64)][kc(4)] { hi[128 rows x 128B SW128], lo[...] }
// ---------------------------------------------------------------------------
__global__ void eblob_kernel(const float* __restrict__ E) {
    int idx = blockIdx.x * 256 + threadIdx.x;
    int k  = idx >> 6;
    int d0 = (idx & 63) * 4;
    const float4 v = *(const float4*)(E + (size_t)k * CH + d0);

    __half h[4], l[4];
    float vv[4] = {v.x, v.y, v.z, v.w};
    #pragma unroll
    for (int q = 0; q < 4; q++) {
        h[q] = __float2half_rn(vv[q]);
        l[q] = __float2half_rn(vv[q] - __half2float(h[q]));
    }
    int ct = k >> 7, row = k & 127, kc = d0 >> 6, col = d0 & 63;
    size_t chunk = ((size_t)(ct * N_CHUNKS + kc)) * STAGE_BYTES;
    uint32_t off = SWZ128((uint32_t)(row * 128 + col * 2));
    *(uint2*)(d_eblob + chunk + off)               = *(uint2*)h;
    *(uint2*)(d_eblob + chunk + CHUNK_BYTES + off) = *(uint2*)l;
}

// ---------------------------------------------------------------------------
// Kernel C: fp16x3 mma.sync GEMM + running argmax of (x.e - 0.5||e||^2).
// SMEM: A_h[4 chunks x 16KB] | A_l[4 x 16KB] | B[2 stages x 32KB] = 192KB
// Final cross-warp merge reuses the B region (dead after the main loop).
// ---------------------------------------------------------------------------
#define SM_A   0
#define SM_AL  65536
#define SM_B   131072
#define SM_TOTAL 196608

__global__ __launch_bounds__(256, 1)
void vq_mma_kernel(const float* __restrict__ X) {
    extern __shared__ char smem[];
    const uint32_t sb = smem_u32(smem);
    const int tid  = threadIdx.x;
    const int wid  = tid >> 5;
    const int lane = tid & 31;
    const int warpM = wid >> 1;      // 0..3  (32-token slab)
    const int warpN = wid & 1;       // 0..1  (64-code slab)
    const int n0 = blockIdx.x * M_TILE;
    const int b  = n0 >> 10;
    const int r0 = n0 & 1023;
    const float* Xb = X + (size_t)b * (CH * HH * WW) + r0;

    auto copy_stage = [&](int it) {
        uint32_t dst = sb + SM_B + (uint32_t)(it & 1) * STAGE_BYTES + tid * 16u;
        const uint8_t* src = d_eblob + (size_t)it * STAGE_BYTES + tid * 16;
        #pragma unroll
        for (int p = 0; p < 8; p++) cpasync16(dst + p * 4096u, src + p * 4096);
        asm volatile("cp.async.commit_group;" ::: "memory");
    };
    copy_stage(0);   // stage 0 in flight during A prologue

    // ---- A prologue: X -> fp16 hi/lo, swizzled chunk layout ----
    #pragma unroll
    for (int l = 0; l < M_TILE * CH / 256; l++) {
        int i = tid + l * 256;
        int d = i >> 7, m = i & 127;
        float v = Xb[(size_t)d * 1024 + m];
        __half h = __float2half_rn(v);
        __half lo = __float2half_rn(v - __half2float(h));
        int chunk = d >> 6, c = d & 63;
        uint32_t off = SWZ128((uint32_t)(m * 128 + c * 2));
        *(__half*)(smem + SM_A  + chunk * CHUNK_BYTES + off) = h;
        *(__half*)(smem + SM_AL + chunk * CHUNK_BYTES + off) = lo;
    }

    // per-lane ldmatrix address components (byte offsets within a chunk)
    const uint32_t a_row = (uint32_t)(warpM * 32 + (lane & 15)) * 128;
    const uint32_t a_col = (uint32_t)(lane >> 4) * 16;              // bytes
    const uint32_t b_row = (uint32_t)(warpN * 64 + (lane & 7) + ((lane >> 4) * 8)) * 128;
    const uint32_t b_col = (uint32_t)((lane >> 3) & 1) * 16;        // bytes

    // running trackers: [mt*2 + half]  (this warp's 64-code slab only)
    float tb1[4], tb2[4]; int ti1[4];
    #pragma unroll
    for (int t = 0; t < 4; t++) { tb1[t] = -FLT_MAX; tb2[t] = -FLT_MAX; ti1[t] = 0; }

    for (int ct = 0; ct < N_TILES; ct++) {
        float acc[2][8][4];
        #pragma unroll
        for (int mt = 0; mt < 2; mt++)
            #pragma unroll
            for (int nt = 0; nt < 8; nt++)
                #pragma unroll
                for (int e = 0; e < 4; e++) acc[mt][nt][e] = 0.f;

        for (int kc = 0; kc < N_CHUNKS; kc++) {
            int it = ct * N_CHUNKS + kc;
            // stage `it` must be fully landed (all threads' cp.async slices)
            asm volatile("cp.async.wait_group 0;" ::: "memory");
            __syncthreads();
            // This barrier also proves all warps finished reading buffer
            // (it-1)&1 == (it+1)&1, so the next-stage copy is safe here.
            if (it + 1 < TOTAL_ITERS) copy_stage(it + 1);

            const uint32_t ah_base = sb + SM_A  + (uint32_t)kc * CHUNK_BYTES;
            const uint32_t al_base = sb + SM_AL + (uint32_t)kc * CHUNK_BYTES;
            const uint32_t bh_base = sb + SM_B + (uint32_t)(it & 1) * STAGE_BYTES;
            const uint32_t bl_base = bh_base + CHUNK_BYTES;

            #pragma unroll
            for (int ks = 0; ks < 4; ks++) {
                const uint32_t kb = (uint32_t)ks * 32;   // bytes (16 dims)
                uint32_t ah[2][4], al[2][4];
                #pragma unroll
                for (int mt = 0; mt < 2; mt++) {
                    uint32_t o = SWZ128(a_row + (uint32_t)mt * 2048 + a_col + kb);
                    ldsm4(ah[mt][0], ah[mt][1], ah[mt][2], ah[mt][3], ah_base + o);
                    ldsm4(al[mt][0], al[mt][1], al[mt][2], al[mt][3], al_base + o);
                }
                uint32_t bh[4][4], bl[4][4];
                #pragma unroll
                for (int np = 0; np < 4; np++) {
                    uint32_t o = SWZ128(b_row + (uint32_t)np * 2048 + b_col + kb);
                    ldsm4(bh[np][0], bh[np][1], bh[np][2], bh[np][3], bh_base + o);
                    ldsm4(bl[np][0], bl[np][1], bl[np][2], bl[np][3], bl_base + o);
                }
                #pragma unroll
                for (int mt = 0; mt < 2; mt++)
                    #pragma unroll
                    for (int nt = 0; nt < 8; nt++) {
                        const int np = nt >> 1, s = (nt & 1) * 2;
                        float* d = acc[mt][nt];
                        mma16816(d[0], d[1], d[2], d[3],
                                 ah[mt][0], ah[mt][1], ah[mt][2], ah[mt][3],
                                 bh[np][s], bh[np][s + 1]);
                        mma16816(d[0], d[1], d[2], d[3],
                                 al[mt][0], al[mt][1], al[mt][2], al[mt][3],
                                 bh[np][s], bh[np][s + 1]);
                        mma16816(d[0], d[1], d[2], d[3],
                                 ah[mt][0], ah[mt][1], ah[mt][2], ah[mt][3],
                                 bl[np][s], bl[np][s + 1]);
                    }
            }
        }

        // ---- epilogue: scores for this 128-code tile (this warp's 64 codes) ----
        const int cb = ct * N_TILE + warpN * 64;
        #pragma unroll
        for (int mt = 0; mt < 2; mt++)
            #pragma unroll
            for (int nt = 0; nt < 8; nt++) {
                int col0 = cb + nt * 8 + (lane & 3) * 2;
                float e0 = 0.5f * __ldg(d_enorm + col0);
                float e1 = 0.5f * __ldg(d_enorm + col0 + 1);
                #pragma unroll
                for (int half = 0; half < 2; half++) {
                    int t = mt * 2 + half;
                    float v0 = acc[mt][nt][half * 2 + 0] - e0;
                    float v1 = acc[mt][nt][half * 2 + 1] - e1;
                    if (v0 > tb1[t]) { tb2[t] = tb1[t]; tb1[t] = v0; ti1[t] = col0; }
                    else if (v0 > tb2[t]) tb2[t] = v0;
                    if (v1 > tb1[t]) { tb2[t] = tb1[t]; tb1[t] = v1; ti1[t] = col0 + 1; }
                    else if (v1 > tb2[t]) tb2[t] = v1;
                }
            }
    }

    // ---- quad reduction within warp (4 lanes share a token row) ----
    #pragma unroll
    for (int t = 0; t < 4; t++) {
        #pragma unroll
        for (int m = 1; m <= 2; m <<= 1) {
            float ob1 = __shfl_xor_sync(0xFFFFFFFFu, tb1[t], m);
            float ob2 = __shfl_xor_sync(0xFFFFFFFFu, tb2[t], m);
            int   oi  = __shfl_xor_sync(0xFFFFFFFFu, ti1[t], m);
            if (ob1 > tb1[t] || (ob1 == tb1[t] && oi < ti1[t])) {
                tb2[t] = fmaxf(tb1[t], ob2);
                tb1[t] = ob1; ti1[t] = oi;
            } else {
                tb2[t] = fmaxf(tb2[t], ob1);
            }
        }
    }

    // ---- cross-warpN merge: each warp only saw half the codes per tile ----
    __syncthreads();                       // B region now dead -> reuse
    float* red_b1 = (float*)(smem + SM_B);          // [2][128]
    float* red_b2 = (float*)(smem + SM_B + 1024);   // [2][128]
    int*   red_i1 = (int*)  (smem + SM_B + 2048);   // [2][128]
    #pragma unroll
    for (int t = 0; t < 4; t++) {
        if ((lane & 3) == 0) {
            int mt = t >> 1, half = t & 1;
            int tl = warpM * 32 + mt * 16 + half * 8 + (lane >> 2);
            red_b1[warpN * 128 + tl] = tb1[t];
            red_b2[warpN * 128 + tl] = tb2[t];
            red_i1[warpN * 128 + tl] = ti1[t];
        }
    }
    __syncthreads();
    if (tid < M_TILE) {
        float a1 = red_b1[tid],       a2 = red_b2[tid];
        int   ai = red_i1[tid];
        float c1 = red_b1[128 + tid], c2 = red_b2[128 + tid];
        int   ci = red_i1[128 + tid];
        float m1, m2; int mi;
        if (c1 > a1 || (c1 == a1 && ci < ai)) { m1 = c1; mi = ci; m2 = fmaxf(a1, c2); }
        else                                   { m1 = a1; mi = ai; m2 = fmaxf(c1, a2); }
        int n = n0 + tid;
        d_idx[n] = mi;
        if (2.0f * (m1 - m2) < MARGIN) {
            int p = atomicAdd(&d_fb_count, 1);
            if (p < NTOK) {
                d_fb_list[p] = n;
                d_fb_best[n] = 0xFFFFFFFFFFFFFFFFull;
            }
        }
    }
}

// ---------------------------------------------------------------------------
// Kernel D: exact fp32 re-scan for flagged tokens, split-K parallel.
// Work item = (token, 256-code segment). 1 code/thread; block-min then one
// atomicMin on an order-encoded (score, idx) key => exact strict-< + low-idx.
// ---------------------------------------------------------------------------
__global__ __launch_bounds__(256)
void fb_kernel(const float* __restrict__ X, const float* __restrict__ E) {
    __shared__ float xs[CH];
    __shared__ unsigned long long red[256];
    const int tid = threadIdx.x;
    int cnt = d_fb_count; if (cnt > NTOK) cnt = NTOK;
    const int total = cnt * FB_SEGS;
    for (int w = blockIdx.x; w < total; w += gridDim.x) {
        const int n   = d_fb_list[w >> 5];
        const int seg = w & (FB_SEGS - 1);
        const int b = n >> 10, r = n & 1023;
        __syncthreads();
        xs[tid] = X[(size_t)b * (CH * HH * WW) + (size_t)tid * 1024 + r];
        __syncthreads();

        const int k = seg * FB_CODES + tid;
        const float4* xs4 = (const float4*)xs;
        const float4* e4  = (const float4*)(E + (size_t)k * CH);
        float s0 = 0.f, s1 = 0.f, s2 = 0.f, s3 = 0.f;
        #pragma unroll 8
        for (int q = 0; q < CH / 4; q++) {
            float4 a = xs4[q]; float4 e = e4[q];
            s0 = fmaf(a.x, e.x, s0); s1 = fmaf(a.y, e.y, s1);
            s2 = fmaf(a.z, e.z, s2); s3 = fmaf(a.w, e.w, s3);
        }
        float dot = (s0 + s1) + (s2 + s3);
        float sc = fmaf(-2.f, dot, d_enorm[k]);
        red[tid] = ((unsigned long long)ord_f32(sc) << 32) | (unsigned)k;
        __syncthreads();
        #pragma unroll
        for (int s = 128; s > 0; s >>= 1) {
            if (tid < s) { unsigned long long o = red[tid + s]; if (o < red[tid]) red[tid] = o; }
            __syncthreads();
        }
        if (tid == 0) atomicMin(&d_fb_best[n], red[0]);
    }
}

__global__ void fb_finalize_kernel() {
    int w = blockIdx.x * 256 + threadIdx.x;
    int cnt = d_fb_count; if (cnt > NTOK) cnt = NTOK;
    if (w < cnt) {
        int n = d_fb_list[w];
        d_idx[n] = (int)(unsigned)(d_fb_best[n] & 0xFFFFFFFFull);
    }
}

// ---------------------------------------------------------------------------
// Kernel E: gather -> quant_out, idx, loss accumulation
// ---------------------------------------------------------------------------
__global__ void gather_loss_kernel(const float* __restrict__ X,
                                   const float* __restrict__ E,
                                   float* __restrict__ out) {
    __shared__ float sdata[256];
    unsigned i = blockIdx.x * 256u + threadIdx.x;
    int w  = i & 31;
    int h  = (i >> 5) & 31;
    int c  = (i >> 10) & 255;
    int bb = i >> 18;
    int n  = bb * 1024 + h * 32 + w;
    int k  = d_idx[n];

    float q = E[(size_t)k * CH + c];
    float x = X[i];
    out[i] = q;
    if (c == 0) out[IDX_OFF + n] = (float)k;

    float d = q - x;
    sdata[threadIdx.x] = d * d;
    __syncthreads();
    #pragma unroll
    for (int s = 128; s > 0; s >>= 1) {
        if (threadIdx.x < s) sdata[threadIdx.x] += sdata[threadIdx.x + s];
        __syncthreads();
    }
    if (threadIdx.x == 0) atomicAdd(&d_loss_acc, (double)sdata[0]);
}

__global__ void finalize_kernel(float* __restrict__ out) {
    out[LOSS_OFF] = (float)(d_loss_acc * 1.25 / (double)QUANT_ELEMS);
}

// ---------------------------------------------------------------------------
extern "C" void kernel_launch(void* const* d_in, const int* in_sizes, int n_in,
                              void* d_out, int out_size) {
    const float* X = (const float*)d_in[0];
    const float* E = (const float*)d_in[1];
    float* out = (float*)d_out;

    cudaFuncSetAttribute(vq_mma_kernel, cudaFuncAttributeMaxDynamicSharedMemorySize, SM_TOTAL);

    prep_kernel<<<KCODE / 8, 256>>>(E);
    eblob_kernel<<<KCODE * CH / 4 / 256, 256>>>(E);
    vq_mma_kernel<<<NTOK / M_TILE, 256, SM_TOTAL>>>(X);
    fb_kernel<<<1024, 256>>>(X, E);
    fb_finalize_kernel<<<NTOK / 256, 256>>>();
    gather_loss_kernel<<<QUANT_ELEMS / 256, 256>>>(X, E, out);
    finalize_kernel<<<1, 1>>>(out);
}

// round 7
// speedup vs baseline: 4.5349x; 1.1752x over previous
#include <cuda_runtime.h>
#include <cuda_fp16.h>
#include <float.h>
#include <stdint.h>

// ---------------------------------------------------------------------------
// Problem constants
// ---------------------------------------------------------------------------
#define BATCH 16
#define CH    256
#define HH    32
#define WW    32
#define NTOK  (BATCH*HH*WW)           // 16384
#define KCODE 8192
#define QUANT_ELEMS (BATCH*CH*HH*WW)  // 4194304
#define LOSS_OFF  QUANT_ELEMS
#define IDX_OFF   (QUANT_ELEMS + 1)

#define M_TILE 128
#define N_TILE 128
#define N_TILES (KCODE / N_TILE)      // 64
#define KC 64                         // dims per chunk
#define N_CHUNKS (CH / KC)            // 4
#define CHUNK_BYTES 16384             // 128 rows x 128B
#define STAGE_BYTES 16384             // hi only (e_l dropped)
#define N_STAGES 4
#define TOTAL_ITERS (N_TILES * N_CHUNKS)  // 256

#define MARGIN 0.05f

#define FBT 16                        // fb tokens per block tile

// ---------------------------------------------------------------------------
// Device scratch (allocation-free)
// ---------------------------------------------------------------------------
__device__ __align__(128) uint8_t d_eblob[(size_t)TOTAL_ITERS * STAGE_BYTES]; // 4 MB
__device__ float  d_enorm[KCODE];
__device__ int    d_idx[NTOK];
__device__ int    d_fb_count;
__device__ int    d_fb_list[NTOK];
__device__ unsigned long long d_fb_best[NTOK];
__device__ double d_loss_acc;

// ---------------------------------------------------------------------------
// Helpers
// ---------------------------------------------------------------------------
__device__ __forceinline__ uint32_t smem_u32(const void* p) {
    uint32_t a;
    asm("{ .reg .u64 t; cvta.to.shared.u64 t, %1; cvt.u32.u64 %0, t; }" : "=r"(a) : "l"(p));
    return a;
}
#define SWZ128(off) ((off) ^ (((off) >> 3) & 0x70))

__device__ __forceinline__ void ldsm4(uint32_t* r, uint32_t addr) {
    asm volatile("ldmatrix.sync.aligned.m8n8.x4.shared.b16 {%0,%1,%2,%3}, [%4];"
                 : "=r"(r[0]), "=r"(r[1]), "=r"(r[2]), "=r"(r[3]) : "r"(addr));
}

__device__ __forceinline__ void mma16816(float* d, const uint32_t* a,
                                         uint32_t b0, uint32_t b1) {
    asm volatile(
        "mma.sync.aligned.m16n8k16.row.col.f32.f16.f16.f32 "
        "{%0,%1,%2,%3}, {%4,%5,%6,%7}, {%8,%9}, {%0,%1,%2,%3};"
        : "+f"(d[0]), "+f"(d[1]), "+f"(d[2]), "+f"(d[3])
        : "r"(a[0]), "r"(a[1]), "r"(a[2]), "r"(a[3]), "r"(b0), "r"(b1));
}

__device__ __forceinline__ void cpasync16(uint32_t dst, const void* src) {
    asm volatile("cp.async.cg.shared.global [%0], [%1], 16;" :: "r"(dst), "l"(src));
}

// order-preserving float->uint map: a < b  <=>  ord(a) < ord(b)
__device__ __forceinline__ unsigned ord_f32(float f) {
    unsigned u = __float_as_uint(f);
    return (u & 0x80000000u) ? ~u : (u | 0x80000000u);
}

// ---------------------------------------------------------------------------
// Kernel A: ||e_k||^2 per code + zero accumulators
// ---------------------------------------------------------------------------
__global__ void prep_kernel(const float* __restrict__ E) {
    if (blockIdx.x == 0 && threadIdx.x == 0) { d_loss_acc = 0.0; d_fb_count = 0; }
    int warp = (blockIdx.x * blockDim.x + threadIdx.x) >> 5;
    int lane = threadIdx.x & 31;
    if (warp < KCODE) {
        const float* row = E + (size_t)warp * CH;
        float s = 0.f;
        #pragma unroll
        for (int d = lane; d < CH; d += 32) { float v = row[d]; s = fmaf(v, v, s); }
        #pragma unroll
        for (int off = 16; off > 0; off >>= 1) s += __shfl_xor_sync(0xFFFFFFFFu, s, off);
        if (lane == 0) d_enorm[warp] = s;
    }
}

// ---------------------------------------------------------------------------
// Kernel B: E -> fp16 (hi only), pre-swizzled chunked blob.
// Layout: [ct(64)][kc(4)] { 128 rows x 128B SW128 }
// ---------------------------------------------------------------------------
__global__ void eblob_kernel(const float* __restrict__ E) {
    int idx = blockIdx.x * 256 + threadIdx.x;
    int k  = idx >> 6;
    int d0 = (idx & 63) * 4;
    const float4 v = *(const float4*)(E + (size_t)k * CH + d0);

    __half h[4];
    h[0] = __float2half_rn(v.x); h[1] = __float2half_rn(v.y);
    h[2] = __float2half_rn(v.z); h[3] = __float2half_rn(v.w);
    int ct = k >> 7, row = k & 127, kc = d0 >> 6, col = d0 & 63;
    size_t chunk = ((size_t)(ct * N_CHUNKS + kc)) * STAGE_BYTES;
    uint32_t off = SWZ128((uint32_t)(row * 128 + col * 2));
    *(uint2*)(d_eblob + chunk + off) = *(uint2*)h;
}

// ---------------------------------------------------------------------------
// Kernel C: 2-term fp16 mma GEMM: x.e_h = (x_h + x_l).e_h, fp32 accum.
// SMEM: A_h[4x16KB] | A_l[4x16KB] | B[4 stages x 16KB] = 192KB
// ---------------------------------------------------------------------------
#define SM_A   0
#define SM_AL  65536
#define SM_B   131072
#define SM_TOTAL 196608

struct Frags { uint32_t ah[2][4]; uint32_t al[2][4]; uint32_t bh[4][4]; };

__global__ __launch_bounds__(256, 1)
void vq_mma_kernel(const float* __restrict__ X) {
    extern __shared__ char smem[];
    const uint32_t sb = smem_u32(smem);
    const int tid  = threadIdx.x;
    const int lane = tid & 31;
    const int wid  = tid >> 5;
    const int warpM = wid >> 1;
    const int warpN = wid & 1;
    const int n0 = blockIdx.x * M_TILE;
    const int b  = n0 >> 10;
    const int r0 = n0 & 1023;
    const float* Xb = X + (size_t)b * (CH * HH * WW) + r0;

    auto copy_stage = [&](int it) {
        uint32_t dst = sb + SM_B + (uint32_t)(it & (N_STAGES-1)) * STAGE_BYTES + tid * 16u;
        const uint8_t* src = d_eblob + (size_t)it * STAGE_BYTES + tid * 16;
        #pragma unroll
        for (int p = 0; p < 4; p++) cpasync16(dst + p * 4096u, src + p * 4096);
        asm volatile("cp.async.commit_group;" ::: "memory");
    };
    copy_stage(0); copy_stage(1); copy_stage(2);

    // ---- A prologue: X -> fp16 hi/lo, swizzled chunk layout ----
    #pragma unroll
    for (int l = 0; l < M_TILE * CH / 256; l++) {
        int i = tid + l * 256;
        int d = i >> 7, m = i & 127;
        float v = Xb[(size_t)d * 1024 + m];
        __half h = __float2half_rn(v);
        __half lo = __float2half_rn(v - __half2float(h));
        int chunk = d >> 6, c = d & 63;
        uint32_t off = SWZ128((uint32_t)(m * 128 + c * 2));
        *(__half*)(smem + SM_A  + chunk * CHUNK_BYTES + off) = h;
        *(__half*)(smem + SM_AL + chunk * CHUNK_BYTES + off) = lo;
    }

    const uint32_t a_row = (uint32_t)(warpM * 32 + (lane & 15)) * 128;
    const uint32_t a_col = (uint32_t)(lane >> 4) * 16;
    const uint32_t b_row = (uint32_t)(warpN * 64 + (lane & 7) + ((lane >> 4) * 8)) * 128;
    const uint32_t b_col = (uint32_t)((lane >> 3) & 1) * 16;

    float tb1[4], tb2[4]; int ti1[4];
    #pragma unroll
    for (int t = 0; t < 4; t++) { tb1[t] = -FLT_MAX; tb2[t] = -FLT_MAX; ti1[t] = 0; }

    for (int ct = 0; ct < N_TILES; ct++) {
        float acc[2][8][4];
        #pragma unroll
        for (int mt = 0; mt < 2; mt++)
            #pragma unroll
            for (int nt = 0; nt < 8; nt++)
                #pragma unroll
                for (int e = 0; e < 4; e++) acc[mt][nt][e] = 0.f;

        for (int kc = 0; kc < N_CHUNKS; kc++) {
            int it = ct * N_CHUNKS + kc;
            // stage `it` landed when <=2 copies remain outstanding
            asm volatile("cp.async.wait_group 2;" ::: "memory");
            __syncthreads();
            // barrier proves all warps finished reading stage (it-1)%4 == (it+3)%4
            if (it + 3 < TOTAL_ITERS) copy_stage(it + 3);

            const uint32_t ah_base = sb + SM_A  + (uint32_t)kc * CHUNK_BYTES;
            const uint32_t al_base = sb + SM_AL + (uint32_t)kc * CHUNK_BYTES;
            const uint32_t bh_base = sb + SM_B + (uint32_t)(it & (N_STAGES-1)) * STAGE_BYTES;

            Frags fr[2];
            auto load_frags = [&](int ks, Frags& f) {
                const uint32_t kb = (uint32_t)ks * 32;
                #pragma unroll
                for (int mt = 0; mt < 2; mt++) {
                    uint32_t o = SWZ128(a_row + (uint32_t)mt * 2048 + a_col + kb);
                    ldsm4(f.ah[mt], ah_base + o);
                    ldsm4(f.al[mt], al_base + o);
                }
                #pragma unroll
                for (int np = 0; np < 4; np++) {
                    uint32_t o = SWZ128(b_row + (uint32_t)np * 2048 + b_col + kb);
                    ldsm4(f.bh[np], bh_base + o);
                }
            };
            auto mma_all = [&](const Frags& f) {
                #pragma unroll
                for (int mt = 0; mt < 2; mt++)
                    #pragma unroll
                    for (int nt = 0; nt < 8; nt++) {
                        const int np = nt >> 1, s = (nt & 1) * 2;
                        mma16816(acc[mt][nt], f.ah[mt], f.bh[np][s], f.bh[np][s + 1]);
                        mma16816(acc[mt][nt], f.al[mt], f.bh[np][s], f.bh[np][s + 1]);
                    }
            };
            // ks-pipelined: prefetch next fragments during MMAs
            load_frags(0, fr[0]);
            load_frags(1, fr[1]);  mma_all(fr[0]);
            load_frags(2, fr[0]);  mma_all(fr[1]);
            load_frags(3, fr[1]);  mma_all(fr[0]);
            mma_all(fr[1]);
        }

        // ---- epilogue: scores for this tile (this warp's 64 codes) ----
        const int cb = ct * N_TILE + warpN * 64;
        #pragma unroll
        for (int mt = 0; mt < 2; mt++)
            #pragma unroll
            for (int nt = 0; nt < 8; nt++) {
                int col0 = cb + nt * 8 + (lane & 3) * 2;
                float e0 = 0.5f * __ldg(d_enorm + col0);
                float e1 = 0.5f * __ldg(d_enorm + col0 + 1);
                #pragma unroll
                for (int half = 0; half < 2; half++) {
                    int t = mt * 2 + half;
                    float v0 = acc[mt][nt][half * 2 + 0] - e0;
                    float v1 = acc[mt][nt][half * 2 + 1] - e1;
                    if (v0 > tb1[t]) { tb2[t] = tb1[t]; tb1[t] = v0; ti1[t] = col0; }
                    else if (v0 > tb2[t]) tb2[t] = v0;
                    if (v1 > tb1[t]) { tb2[t] = tb1[t]; tb1[t] = v1; ti1[t] = col0 + 1; }
                    else if (v1 > tb2[t]) tb2[t] = v1;
                }
            }
    }

    // ---- quad reduction within warp ----
    #pragma unroll
    for (int t = 0; t < 4; t++) {
        #pragma unroll
        for (int m = 1; m <= 2; m <<= 1) {
            float ob1 = __shfl_xor_sync(0xFFFFFFFFu, tb1[t], m);
            float ob2 = __shfl_xor_sync(0xFFFFFFFFu, tb2[t], m);
            int   oi  = __shfl_xor_sync(0xFFFFFFFFu, ti1[t], m);
            if (ob1 > tb1[t] || (ob1 == tb1[t] && oi < ti1[t])) {
                tb2[t] = fmaxf(tb1[t], ob2);
                tb1[t] = ob1; ti1[t] = oi;
            } else {
                tb2[t] = fmaxf(tb2[t], ob1);
            }
        }
    }

    // ---- cross-warpN merge (reuse dead B region) ----
    __syncthreads();
    float* red_b1 = (float*)(smem + SM_B);
    float* red_b2 = (float*)(smem + SM_B + 1024);
    int*   red_i1 = (int*)  (smem + SM_B + 2048);
    #pragma unroll
    for (int t = 0; t < 4; t++) {
        if ((lane & 3) == 0) {
            int mt = t >> 1, half = t & 1;
            int tl = warpM * 32 + mt * 16 + half * 8 + (lane >> 2);
            red_b1[warpN * 128 + tl] = tb1[t];
            red_b2[warpN * 128 + tl] = tb2[t];
            red_i1[warpN * 128 + tl] = ti1[t];
        }
    }
    __syncthreads();
    if (tid < M_TILE) {
        float a1 = red_b1[tid],       a2 = red_b2[tid];
        int   ai = red_i1[tid];
        float c1 = red_b1[128 + tid], c2 = red_b2[128 + tid];
        int   ci = red_i1[128 + tid];
        float m1, m2; int mi;
        if (c1 > a1 || (c1 == a1 && ci < ai)) { m1 = c1; mi = ci; m2 = fmaxf(a1, c2); }
        else                                   { m1 = a1; mi = ai; m2 = fmaxf(c1, a2); }
        int n = n0 + tid;
        d_idx[n] = mi;
        if (2.0f * (m1 - m2) < MARGIN) {
            int p = atomicAdd(&d_fb_count, 1);
            if (p < NTOK) {
                d_fb_list[p] = n;
                d_fb_best[n] = 0xFFFFFFFFFFFFFFFFull;
            }
        }
    }
}

// ---------------------------------------------------------------------------
// Kernel D: exact fp32 rescan as mini-GEMM tiles.
// Work item = (token-group of 16, 128-code segment). 128 threads: one code
// per thread, x-tile (16 tokens) resident in smem. Block top-1 per token via
// smem+shfl, one atomicMin per token per block on ord-encoded key.
// ---------------------------------------------------------------------------
__global__ __launch_bounds__(128)
void fb_kernel(const float* __restrict__ X, const float* __restrict__ E) {
    __shared__ float xs[FBT][CH];                      // 16 KB
    __shared__ unsigned long long red[FBT][128];       // 16 KB
    const int tid = threadIdx.x;
    int cnt = d_fb_count; if (cnt > NTOK) cnt = NTOK;
    const int ngrp = (cnt + FBT - 1) / FBT;
    const int items = ngrp * (KCODE / 128);
    for (int w = blockIdx.x; w < items; w += gridDim.x) {
        const int grp = w >> 6, seg = w & 63;
        __syncthreads();
        for (int i = tid; i < FBT * CH; i += 128) {
            int t = i >> 8, d = i & 255;
            int li = grp * FBT + t;
            int n = d_fb_list[li < cnt ? li : 0];
            int b = n >> 10, r = n & 1023;
            xs[t][d] = X[(size_t)b * (CH * HH * WW) + (size_t)d * 1024 + r];
        }
        __syncthreads();

        const int c = seg * 128 + tid;
        const float4* e4 = (const float4*)(E + (size_t)c * CH);
        float dots[FBT];
        #pragma unroll
        for (int t = 0; t < FBT; t++) dots[t] = 0.f;
        #pragma unroll 4
        for (int q = 0; q < CH / 4; q++) {
            float4 e = e4[q];
            #pragma unroll
            for (int t = 0; t < FBT; t++) {
                float4 a = *(const float4*)&xs[t][q * 4];
                dots[t] = fmaf(a.x, e.x, fmaf(a.y, e.y, fmaf(a.z, e.z, fmaf(a.w, e.w, dots[t]))));
            }
        }
        float en = d_enorm[c];
        #pragma unroll
        for (int t = 0; t < FBT; t++) {
            float sc = fmaf(-2.f, dots[t], en);
            red[t][tid] = ((unsigned long long)ord_f32(sc) << 32) | (unsigned)c;
        }
        __syncthreads();
        // token t handled by 8 threads (tid/8 == t)
        {
            int t = tid >> 3, l8 = tid & 7;
            unsigned long long m = 0xFFFFFFFFFFFFFFFFull;
            #pragma unroll
            for (int j = 0; j < 16; j++) {
                unsigned long long v = red[t][l8 + j * 8];
                if (v < m) m = v;
            }
            #pragma unroll
            for (int o = 4; o > 0; o >>= 1) {
                unsigned long long v = __shfl_xor_sync(0xFFFFFFFFu, m, o);
                if (v < m) m = v;
            }
            int li = grp * FBT + t;
            if (l8 == 0 && li < cnt) atomicMin(&d_fb_best[d_fb_list[li]], m);
        }
    }
}

__global__ void fb_finalize_kernel() {
    int w = blockIdx.x * 256 + threadIdx.x;
    int cnt = d_fb_count; if (cnt > NTOK) cnt = NTOK;
    if (w < cnt) {
        int n = d_fb_list[w];
        d_idx[n] = (int)(unsigned)(d_fb_best[n] & 0xFFFFFFFFull);
    }
}

// ---------------------------------------------------------------------------
// Kernel E: gather -> quant_out, idx, loss accumulation
// ---------------------------------------------------------------------------
__global__ void gather_loss_kernel(const float* __restrict__ X,
                                   const float* __restrict__ E,
                                   float* __restrict__ out) {
    __shared__ float sdata[256];
    unsigned i = blockIdx.x * 256u + threadIdx.x;
    int w  = i & 31;
    int h  = (i >> 5) & 31;
    int c  = (i >> 10) & 255;
    int bb = i >> 18;
    int n  = bb * 1024 + h * 32 + w;
    int k  = d_idx[n];

    float q = E[(size_t)k * CH + c];
    float x = X[i];
    out[i] = q;
    if (c == 0) out[IDX_OFF + n] = (float)k;

    float d = q - x;
    sdata[threadIdx.x] = d * d;
    __syncthreads();
    #pragma unroll
    for (int s = 128; s > 0; s >>= 1) {
        if (threadIdx.x < s) sdata[threadIdx.x] += sdata[threadIdx.x + s];
        __syncthreads();
    }
    if (threadIdx.x == 0) atomicAdd(&d_loss_acc, (double)sdata[0]);
}

__global__ void finalize_kernel(float* __restrict__ out) {
    out[LOSS_OFF] = (float)(d_loss_acc * 1.25 / (double)QUANT_ELEMS);
}

// ---------------------------------------------------------------------------
extern "C" void kernel_launch(void* const* d_in, const int* in_sizes, int n_in,
                              void* d_out, int out_size) {
    const float* X = (const float*)d_in[0];
    const float* E = (const float*)d_in[1];
    float* out = (float*)d_out;

    cudaFuncSetAttribute(vq_mma_kernel, cudaFuncAttributeMaxDynamicSharedMemorySize, SM_TOTAL);

    prep_kernel<<<KCODE / 8, 256>>>(E);
    eblob_kernel<<<KCODE * CH / 4 / 256, 256>>>(E);
    vq_mma_kernel<<<NTOK / M_TILE, 256, SM_TOTAL>>>(X);
    fb_kernel<<<1024, 128>>>(X, E);
    fb_finalize_kernel<<<NTOK / 256, 256>>>();
    gather_loss_kernel<<<QUANT_ELEMS / 256, 256>>>(X, E, out);
    finalize_kernel<<<1, 1>>>(out);
}

// round 8
// speedup vs baseline: 6.2767x; 1.3841x over previous
#include <cuda_runtime.h>
#include <cuda_fp16.h>
#include <float.h>
#include <stdint.h>

// ---------------------------------------------------------------------------
// Problem constants
// ---------------------------------------------------------------------------
#define BATCH 16
#define CH    256
#define HH    32
#define WW    32
#define NTOK  (BATCH*HH*WW)           // 16384
#define KCODE 8192
#define QUANT_ELEMS (BATCH*CH*HH*WW)  // 4194304
#define LOSS_OFF  QUANT_ELEMS
#define IDX_OFF   (QUANT_ELEMS + 1)

#define M_TILE 128
#define N_TILE 128
#define N_TILES (KCODE / N_TILE)      // 64
#define KC 64
#define N_CHUNKS (CH / KC)            // 4
#define CHUNK_BYTES 16384             // 128 rows x 128B
#define STAGE_BYTES 16384
#define N_STAGES 6
#define TOTAL_ITERS (N_TILES * N_CHUNKS)  // 256

// 2*B where B = 12-sigma bound on the 1-term fp16 v-score error (std ~6.3e-3)
#define WIN2B 0.15f

#define FBT 16

// ---------------------------------------------------------------------------
// Device scratch (allocation-free)
// ---------------------------------------------------------------------------
__device__ __align__(128) uint8_t d_eblob[(size_t)TOTAL_ITERS * STAGE_BYTES]; // 4 MB
__device__ float  d_enorm[KCODE];
__device__ int    d_idx[NTOK];
// refine list (exact 2-code compare)
__device__ int    d_ref_count;
__device__ int    d_ref_n[NTOK];
__device__ int    d_ref_i1[NTOK];
__device__ int    d_ref_i2[NTOK];
// full-rescan list
__device__ int    d_fb_count;
__device__ int    d_fb_list[NTOK];
__device__ unsigned long long d_fb_best[NTOK];
__device__ double d_loss_acc;

// ---------------------------------------------------------------------------
// Helpers
// ---------------------------------------------------------------------------
__device__ __forceinline__ uint32_t smem_u32(const void* p) {
    uint32_t a;
    asm("{ .reg .u64 t; cvta.to.shared.u64 t, %1; cvt.u32.u64 %0, t; }" : "=r"(a) : "l"(p));
    return a;
}
#define SWZ128(off) ((off) ^ (((off) >> 3) & 0x70))

__device__ __forceinline__ void ldsm4(uint32_t* r, uint32_t addr) {
    asm volatile("ldmatrix.sync.aligned.m8n8.x4.shared.b16 {%0,%1,%2,%3}, [%4];"
                 : "=r"(r[0]), "=r"(r[1]), "=r"(r[2]), "=r"(r[3]) : "r"(addr));
}

__device__ __forceinline__ void mma16816(float* d, const uint32_t* a,
                                         uint32_t b0, uint32_t b1) {
    asm volatile(
        "mma.sync.aligned.m16n8k16.row.col.f32.f16.f16.f32 "
        "{%0,%1,%2,%3}, {%4,%5,%6,%7}, {%8,%9}, {%0,%1,%2,%3};"
        : "+f"(d[0]), "+f"(d[1]), "+f"(d[2]), "+f"(d[3])
        : "r"(a[0]), "r"(a[1]), "r"(a[2]), "r"(a[3]), "r"(b0), "r"(b1));
}

__device__ __forceinline__ void cpasync16(uint32_t dst, const void* src) {
    asm volatile("cp.async.cg.shared.global [%0], [%1], 16;" :: "r"(dst), "l"(src));
}

__device__ __forceinline__ unsigned ord_f32(float f) {
    unsigned u = __float_as_uint(f);
    return (u & 0x80000000u) ? ~u : (u | 0x80000000u);
}

// top-3 (max) insert
__device__ __forceinline__ void ins3(float v, int i,
                                     float& v1, float& v2, float& v3,
                                     int& i1, int& i2, int& i3) {
    if (v > v3) {
        if (v > v1)      { v3 = v2; i3 = i2; v2 = v1; i2 = i1; v1 = v; i1 = i; }
        else if (v > v2) { v3 = v2; i3 = i2; v2 = v;  i2 = i; }
        else             { v3 = v;  i3 = i; }
    }
}

// ---------------------------------------------------------------------------
// Kernel A: ||e_k||^2 per code + zero accumulators
// ---------------------------------------------------------------------------
__global__ void prep_kernel(const float* __restrict__ E) {
    if (blockIdx.x == 0 && threadIdx.x == 0) {
        d_loss_acc = 0.0; d_fb_count = 0; d_ref_count = 0;
    }
    int warp = (blockIdx.x * blockDim.x + threadIdx.x) >> 5;
    int lane = threadIdx.x & 31;
    if (warp < KCODE) {
        const float* row = E + (size_t)warp * CH;
        float s = 0.f;
        #pragma unroll
        for (int d = lane; d < CH; d += 32) { float v = row[d]; s = fmaf(v, v, s); }
        #pragma unroll
        for (int off = 16; off > 0; off >>= 1) s += __shfl_xor_sync(0xFFFFFFFFu, s, off);
        if (lane == 0) d_enorm[warp] = s;
    }
}

// ---------------------------------------------------------------------------
// Kernel B: E -> fp16, pre-swizzled chunked blob
// ---------------------------------------------------------------------------
__global__ void eblob_kernel(const float* __restrict__ E) {
    int idx = blockIdx.x * 256 + threadIdx.x;
    int k  = idx >> 6;
    int d0 = (idx & 63) * 4;
    const float4 v = *(const float4*)(E + (size_t)k * CH + d0);
    __half h[4];
    h[0] = __float2half_rn(v.x); h[1] = __float2half_rn(v.y);
    h[2] = __float2half_rn(v.z); h[3] = __float2half_rn(v.w);
    int ct = k >> 7, row = k & 127, kc = d0 >> 6, col = d0 & 63;
    size_t chunk = ((size_t)(ct * N_CHUNKS + kc)) * STAGE_BYTES;
    uint32_t off = SWZ128((uint32_t)(row * 128 + col * 2));
    *(uint2*)(d_eblob + chunk + off) = *(uint2*)h;
}

// ---------------------------------------------------------------------------
// Kernel C: 1-term fp16 mma GEMM + top-3 tracking of v = x.e - 0.5||e||^2
// SMEM: A_h[4x16KB]=64KB | B[6 stages x 16KB]=96KB  -> 160KB
// ---------------------------------------------------------------------------
#define SM_A   0
#define SM_B   65536
#define SM_TOTAL 163840

struct Frags { uint32_t ah[2][4]; uint32_t bh[4][4]; };

__global__ __launch_bounds__(256, 1)
void vq_mma_kernel(const float* __restrict__ X) {
    extern __shared__ char smem[];
    const uint32_t sb = smem_u32(smem);
    const int tid  = threadIdx.x;
    const int lane = tid & 31;
    const int wid  = tid >> 5;
    const int warpM = wid >> 1;
    const int warpN = wid & 1;
    const int n0 = blockIdx.x * M_TILE;
    const int b  = n0 >> 10;
    const int r0 = n0 & 1023;
    const float* Xb = X + (size_t)b * (CH * HH * WW) + r0;

    auto copy_stage = [&](int it) {
        uint32_t dst = sb + SM_B + (uint32_t)(it % N_STAGES) * STAGE_BYTES + tid * 16u;
        const uint8_t* src = d_eblob + (size_t)it * STAGE_BYTES + tid * 16;
        #pragma unroll
        for (int p = 0; p < 4; p++) cpasync16(dst + p * 4096u, src + p * 4096);
        asm volatile("cp.async.commit_group;" ::: "memory");
    };
    copy_stage(0); copy_stage(1); copy_stage(2); copy_stage(3); copy_stage(4);

    // ---- A prologue: X -> fp16, swizzled chunk layout ----
    #pragma unroll
    for (int l = 0; l < M_TILE * CH / 256; l++) {
        int i = tid + l * 256;
        int d = i >> 7, m = i & 127;
        float v = Xb[(size_t)d * 1024 + m];
        int chunk = d >> 6, c = d & 63;
        uint32_t off = SWZ128((uint32_t)(m * 128 + c * 2));
        *(__half*)(smem + SM_A + chunk * CHUNK_BYTES + off) = __float2half_rn(v);
    }

    const uint32_t a_row = (uint32_t)(warpM * 32 + (lane & 15)) * 128;
    const uint32_t a_col = (uint32_t)(lane >> 4) * 16;
    const uint32_t b_row = (uint32_t)(warpN * 64 + (lane & 7) + ((lane >> 4) * 8)) * 128;
    const uint32_t b_col = (uint32_t)((lane >> 3) & 1) * 16;

    // per-token-slot top-3: t in [0,4)
    float tv1[4], tv2[4], tv3[4]; int ti1[4], ti2[4], ti3[4];
    #pragma unroll
    for (int t = 0; t < 4; t++) {
        tv1[t] = tv2[t] = tv3[t] = -FLT_MAX;
        ti1[t] = ti2[t] = ti3[t] = 0;
    }

    for (int ct = 0; ct < N_TILES; ct++) {
        float acc[2][8][4];
        #pragma unroll
        for (int mt = 0; mt < 2; mt++)
            #pragma unroll
            for (int nt = 0; nt < 8; nt++)
                #pragma unroll
                for (int e = 0; e < 4; e++) acc[mt][nt][e] = 0.f;

        for (int kc = 0; kc < N_CHUNKS; kc++) {
            int it = ct * N_CHUNKS + kc;
            asm volatile("cp.async.wait_group 4;" ::: "memory");
            __syncthreads();
            // barrier proves all warps done reading stage (it+5)%6 == (it-1)%6
            if (it + 5 < TOTAL_ITERS) copy_stage(it + 5);

            const uint32_t ah_base = sb + SM_A + (uint32_t)kc * CHUNK_BYTES;
            const uint32_t bh_base = sb + SM_B + (uint32_t)(it % N_STAGES) * STAGE_BYTES;

            Frags fr[2];
            auto load_frags = [&](int ks, Frags& f) {
                const uint32_t kb = (uint32_t)ks * 32;
                #pragma unroll
                for (int mt = 0; mt < 2; mt++)
                    ldsm4(f.ah[mt], ah_base + SWZ128(a_row + (uint32_t)mt * 2048 + a_col + kb));
                #pragma unroll
                for (int np = 0; np < 4; np++)
                    ldsm4(f.bh[np], bh_base + SWZ128(b_row + (uint32_t)np * 2048 + b_col + kb));
            };
            auto mma_all = [&](const Frags& f) {
                #pragma unroll
                for (int mt = 0; mt < 2; mt++)
                    #pragma unroll
                    for (int nt = 0; nt < 8; nt++) {
                        const int np = nt >> 1, s = (nt & 1) * 2;
                        mma16816(acc[mt][nt], f.ah[mt], f.bh[np][s], f.bh[np][s + 1]);
                    }
            };
            load_frags(0, fr[0]);
            load_frags(1, fr[1]);  mma_all(fr[0]);
            load_frags(2, fr[0]);  mma_all(fr[1]);
            load_frags(3, fr[1]);  mma_all(fr[0]);
            mma_all(fr[1]);
        }

        // ---- epilogue: v = dot - 0.5||e||^2, top-3 insert ----
        const int cb = ct * N_TILE + warpN * 64;
        #pragma unroll
        for (int mt = 0; mt < 2; mt++)
            #pragma unroll
            for (int nt = 0; nt < 8; nt++) {
                int col0 = cb + nt * 8 + (lane & 3) * 2;
                float e0 = 0.5f * __ldg(d_enorm + col0);
                float e1 = 0.5f * __ldg(d_enorm + col0 + 1);
                #pragma unroll
                for (int half = 0; half < 2; half++) {
                    int t = mt * 2 + half;
                    float v0 = acc[mt][nt][half * 2 + 0] - e0;
                    float v1 = acc[mt][nt][half * 2 + 1] - e1;
                    ins3(v0, col0,     tv1[t], tv2[t], tv3[t], ti1[t], ti2[t], ti3[t]);
                    ins3(v1, col0 + 1, tv1[t], tv2[t], tv3[t], ti1[t], ti2[t], ti3[t]);
                }
            }
    }

    // ---- quad reduction within warp: merge top-3 sets ----
    #pragma unroll
    for (int t = 0; t < 4; t++) {
        #pragma unroll
        for (int m = 1; m <= 2; m <<= 1) {
            float ov1 = __shfl_xor_sync(0xFFFFFFFFu, tv1[t], m);
            float ov2 = __shfl_xor_sync(0xFFFFFFFFu, tv2[t], m);
            float ov3 = __shfl_xor_sync(0xFFFFFFFFu, tv3[t], m);
            int   oi1 = __shfl_xor_sync(0xFFFFFFFFu, ti1[t], m);
            int   oi2 = __shfl_xor_sync(0xFFFFFFFFu, ti2[t], m);
            int   oi3 = __shfl_xor_sync(0xFFFFFFFFu, ti3[t], m);
            ins3(ov1, oi1, tv1[t], tv2[t], tv3[t], ti1[t], ti2[t], ti3[t]);
            ins3(ov2, oi2, tv1[t], tv2[t], tv3[t], ti1[t], ti2[t], ti3[t]);
            ins3(ov3, oi3, tv1[t], tv2[t], tv3[t], ti1[t], ti2[t], ti3[t]);
        }
    }

    // ---- cross-warpN merge via smem (B region dead) ----
    __syncthreads();
    float* rv1 = (float*)(smem + SM_B);
    float* rv2 = (float*)(smem + SM_B + 1024);
    float* rv3 = (float*)(smem + SM_B + 2048);
    int*   ri1 = (int*)  (smem + SM_B + 3072);
    int*   ri2 = (int*)  (smem + SM_B + 4096);
    int*   ri3 = (int*)  (smem + SM_B + 5120);
    #pragma unroll
    for (int t = 0; t < 4; t++) {
        if ((lane & 3) == 0) {
            int mt = t >> 1, half = t & 1;
            int tl = warpN * 128 + warpM * 32 + mt * 16 + half * 8 + (lane >> 2);
            rv1[tl] = tv1[t]; rv2[tl] = tv2[t]; rv3[tl] = tv3[t];
            ri1[tl] = ti1[t]; ri2[tl] = ti2[t]; ri3[tl] = ti3[t];
        }
    }
    __syncthreads();
    if (tid < M_TILE) {
        float v1 = rv1[tid], v2 = rv2[tid], v3 = rv3[tid];
        int   i1 = ri1[tid], i2 = ri2[tid], i3 = ri3[tid];
        ins3(rv1[128 + tid], ri1[128 + tid], v1, v2, v3, i1, i2, i3);
        ins3(rv2[128 + tid], ri2[128 + tid], v1, v2, v3, i1, i2, i3);
        ins3(rv3[128 + tid], ri3[128 + tid], v1, v2, v3, i1, i2, i3);
        int n = n0 + tid;
        d_idx[n] = i1;
        if (v1 - v3 < WIN2B) {
            // can't certify candidate set -> full exact rescan
            int p = atomicAdd(&d_fb_count, 1);
            if (p < NTOK) { d_fb_list[p] = n; d_fb_best[n] = 0xFFFFFFFFFFFFFFFFull; }
        } else if (v1 - v2 < WIN2B) {
            // true argmin provably in {i1, i2}: exact 2-code refine
            int p = atomicAdd(&d_ref_count, 1);
            if (p < NTOK) { d_ref_n[p] = n; d_ref_i1[p] = i1; d_ref_i2[p] = i2; }
        }
    }
}

// ---------------------------------------------------------------------------
// Kernel D1: exact fp32 refine of 2 candidate codes. One warp per token.
// ---------------------------------------------------------------------------
__global__ __launch_bounds__(256)
void refine_kernel(const float* __restrict__ X, const float* __restrict__ E) {
    const int lane = threadIdx.x & 31;
    const int gw = blockIdx.x * 8 + (threadIdx.x >> 5);
    int cnt = d_ref_count; if (cnt > NTOK) cnt = NTOK;
    for (int w = gw; w < cnt; w += gridDim.x * 8) {
        int n = d_ref_n[w], i1 = d_ref_i1[w], i2 = d_ref_i2[w];
        int b = n >> 10, r = n & 1023;
        const float* Xp = X + (size_t)b * (CH * HH * WW) + r;
        const float* e1 = E + (size_t)i1 * CH;
        const float* e2 = E + (size_t)i2 * CH;
        float s1 = 0.f, s2 = 0.f;
        #pragma unroll
        for (int j = 0; j < CH / 32; j++) {
            int d = lane + j * 32;
            float x = Xp[(size_t)d * 1024];
            s1 = fmaf(x, e1[d], s1);
            s2 = fmaf(x, e2[d], s2);
        }
        #pragma unroll
        for (int o = 16; o > 0; o >>= 1) {
            s1 += __shfl_xor_sync(0xFFFFFFFFu, s1, o);
            s2 += __shfl_xor_sync(0xFFFFFFFFu, s2, o);
        }
        if (lane == 0) {
            float sc1 = fmaf(-2.f, s1, d_enorm[i1]);
            float sc2 = fmaf(-2.f, s2, d_enorm[i2]);
            int win = (sc2 < sc1 || (sc2 == sc1 && i2 < i1)) ? i2 : i1;
            d_idx[n] = win;
        }
    }
}

// ---------------------------------------------------------------------------
// Kernel D2: full exact fp32 rescan (rare), mini-GEMM tiles.
// ---------------------------------------------------------------------------
__global__ __launch_bounds__(128)
void fb_kernel(const float* __restrict__ X, const float* __restrict__ E) {
    __shared__ float xs[FBT][CH];
    __shared__ unsigned long long red[FBT][128];
    const int tid = threadIdx.x;
    int cnt = d_fb_count; if (cnt > NTOK) cnt = NTOK;
    const int ngrp = (cnt + FBT - 1) / FBT;
    const int items = ngrp * (KCODE / 128);
    for (int w = blockIdx.x; w < items; w += gridDim.x) {
        const int grp = w >> 6, seg = w & 63;
        __syncthreads();
        for (int i = tid; i < FBT * CH; i += 128) {
            int t = i >> 8, d = i & 255;
            int li = grp * FBT + t;
            int n = d_fb_list[li < cnt ? li : 0];
            int b = n >> 10, r = n & 1023;
            xs[t][d] = X[(size_t)b * (CH * HH * WW) + (size_t)d * 1024 + r];
        }
        __syncthreads();
        const int c = seg * 128 + tid;
        const float4* e4 = (const float4*)(E + (size_t)c * CH);
        float dots[FBT];
        #pragma unroll
        for (int t = 0; t < FBT; t++) dots[t] = 0.f;
        #pragma unroll 4
        for (int q = 0; q < CH / 4; q++) {
            float4 e = e4[q];
            #pragma unroll
            for (int t = 0; t < FBT; t++) {
                float4 a = *(const float4*)&xs[t][q * 4];
                dots[t] = fmaf(a.x, e.x, fmaf(a.y, e.y, fmaf(a.z, e.z, fmaf(a.w, e.w, dots[t]))));
            }
        }
        float en = d_enorm[c];
        #pragma unroll
        for (int t = 0; t < FBT; t++) {
            float sc = fmaf(-2.f, dots[t], en);
            red[t][tid] = ((unsigned long long)ord_f32(sc) << 32) | (unsigned)c;
        }
        __syncthreads();
        {
            int t = tid >> 3, l8 = tid & 7;
            unsigned long long m = 0xFFFFFFFFFFFFFFFFull;
            #pragma unroll
            for (int j = 0; j < 16; j++) {
                unsigned long long v = red[t][l8 + j * 8];
                if (v < m) m = v;
            }
            #pragma unroll
            for (int o = 4; o > 0; o >>= 1) {
                unsigned long long v = __shfl_xor_sync(0xFFFFFFFFu, m, o);
                if (v < m) m = v;
            }
            int li = grp * FBT + t;
            if (l8 == 0 && li < cnt) atomicMin(&d_fb_best[d_fb_list[li]], m);
        }
    }
}

__global__ void fb_finalize_kernel() {
    int w = blockIdx.x * 256 + threadIdx.x;
    int cnt = d_fb_count; if (cnt > NTOK) cnt = NTOK;
    if (w < cnt) {
        int n = d_fb_list[w];
        d_idx[n] = (int)(unsigned)(d_fb_best[n] & 0xFFFFFFFFull);
    }
}

// ---------------------------------------------------------------------------
// Kernel E: gather -> quant_out, idx, loss accumulation
// ---------------------------------------------------------------------------
__global__ void gather_loss_kernel(const float* __restrict__ X,
                                   const float* __restrict__ E,
                                   float* __restrict__ out) {
    __shared__ float sdata[256];
    unsigned i = blockIdx.x * 256u + threadIdx.x;
    int w  = i & 31;
    int h  = (i >> 5) & 31;
    int c  = (i >> 10) & 255;
    int bb = i >> 18;
    int n  = bb * 1024 + h * 32 + w;
    int k  = d_idx[n];

    float q = E[(size_t)k * CH + c];
    float x = X[i];
    out[i] = q;
    if (c == 0) out[IDX_OFF + n] = (float)k;

    float d = q - x;
    sdata[threadIdx.x] = d * d;
    __syncthreads();
    #pragma unroll
    for (int s = 128; s > 0; s >>= 1) {
        if (threadIdx.x < s) sdata[threadIdx.x] += sdata[threadIdx.x + s];
        __syncthreads();
    }
    if (threadIdx.x == 0) atomicAdd(&d_loss_acc, (double)sdata[0]);
}

__global__ void finalize_kernel(float* __restrict__ out) {
    out[LOSS_OFF] = (float)(d_loss_acc * 1.25 / (double)QUANT_ELEMS);
}

// ---------------------------------------------------------------------------
extern "C" void kernel_launch(void* const* d_in, const int* in_sizes, int n_in,
                              void* d_out, int out_size) {
    const float* X = (const float*)d_in[0];
    const float* E = (const float*)d_in[1];
    float* out = (float*)d_out;

    cudaFuncSetAttribute(vq_mma_kernel, cudaFuncAttributeMaxDynamicSharedMemorySize, SM_TOTAL);

    prep_kernel<<<KCODE / 8, 256>>>(E);
    eblob_kernel<<<KCODE * CH / 4 / 256, 256>>>(E);
    vq_mma_kernel<<<NTOK / M_TILE, 256, SM_TOTAL>>>(X);
    refine_kernel<<<128, 256>>>(X, E);
    fb_kernel<<<256, 128>>>(X, E);
    fb_finalize_kernel<<<NTOK / 256, 256>>>();
    gather_loss_kernel<<<QUANT_ELEMS / 256, 256>>>(X, E, out);
    finalize_kernel<<<1, 1>>>(out);
}

// round 9
// speedup vs baseline: 7.1971x; 1.1466x over previous
#include <cuda_runtime.h>
#include <cuda_fp16.h>
#include <float.h>
#include <stdint.h>

// ---------------------------------------------------------------------------
// Problem constants
// ---------------------------------------------------------------------------
#define BATCH 16
#define CH    256
#define HH    32
#define WW    32
#define NTOK  (BATCH*HH*WW)           // 16384
#define KCODE 8192
#define QUANT_ELEMS (BATCH*CH*HH*WW)  // 4194304
#define LOSS_OFF  QUANT_ELEMS
#define IDX_OFF   (QUANT_ELEMS + 1)

#define M_TILE 128
#define N_TILE 128
#define N_TILES (KCODE / N_TILE)      // 64
#define KC 64
#define N_CHUNKS (CH / KC)            // 4
#define CHUNK_BYTES 16384             // 128 rows x 128B
#define STAGE_BYTES 16384
#define N_STAGES 6
#define TOTAL_ITERS (N_TILES * N_CHUNKS)  // 256

// 2*B, B = 12-sigma bound on 1-term fp16 v-score error (std ~6.3e-3)
#define WIN2B 0.15f

#define FBT 16

// ---------------------------------------------------------------------------
// Device scratch (allocation-free)
// ---------------------------------------------------------------------------
__device__ __align__(128) uint8_t d_eblob[(size_t)TOTAL_ITERS * STAGE_BYTES]; // 4 MB
__device__ float  d_enorm[KCODE];
__device__ float  d_enorm05[KCODE];
__device__ int    d_idx[NTOK];
__device__ int    d_ref_count;
__device__ int    d_ref_n[NTOK];
__device__ int    d_ref_i1[NTOK];
__device__ int    d_ref_i2[NTOK];
__device__ int    d_fb_count;
__device__ int    d_fb_list[NTOK];
__device__ unsigned long long d_fb_best[NTOK];
__device__ double d_loss_acc;

// ---------------------------------------------------------------------------
// Helpers
// ---------------------------------------------------------------------------
__device__ __forceinline__ uint32_t smem_u32(const void* p) {
    uint32_t a;
    asm("{ .reg .u64 t; cvta.to.shared.u64 t, %1; cvt.u32.u64 %0, t; }" : "=r"(a) : "l"(p));
    return a;
}
#define SWZ128(off) ((off) ^ (((off) >> 3) & 0x70))

__device__ __forceinline__ void ldsm4(uint32_t* r, uint32_t addr) {
    asm volatile("ldmatrix.sync.aligned.m8n8.x4.shared.b16 {%0,%1,%2,%3}, [%4];"
                 : "=r"(r[0]), "=r"(r[1]), "=r"(r[2]), "=r"(r[3]) : "r"(addr));
}

__device__ __forceinline__ void mma16816(float* d, const uint32_t* a,
                                         uint32_t b0, uint32_t b1) {
    asm volatile(
        "mma.sync.aligned.m16n8k16.row.col.f32.f16.f16.f32 "
        "{%0,%1,%2,%3}, {%4,%5,%6,%7}, {%8,%9}, {%0,%1,%2,%3};"
        : "+f"(d[0]), "+f"(d[1]), "+f"(d[2]), "+f"(d[3])
        : "r"(a[0]), "r"(a[1]), "r"(a[2]), "r"(a[3]), "r"(b0), "r"(b1));
}

__device__ __forceinline__ void cpasync16(uint32_t dst, const void* src) {
    asm volatile("cp.async.cg.shared.global [%0], [%1], 16;" :: "r"(dst), "l"(src));
}

__device__ __forceinline__ unsigned ord_f32(float f) {
    unsigned u = __float_as_uint(f);
    return (u & 0x80000000u) ? ~u : (u | 0x80000000u);
}

// top-3 insert; third slot is value-only (index never needed: a 3rd-best
// from one partial can never rank top-2 in a merged set).
__device__ __forceinline__ void ins3vi(float v, int i,
                                       float& v1, int& i1,
                                       float& v2, int& i2, float& v3) {
    if (v > v3) {
        if (v > v1)      { v3 = v2; v2 = v1; i2 = i1; v1 = v; i1 = i; }
        else if (v > v2) { v3 = v2; v2 = v;  i2 = i; }
        else             { v3 = v; }
    }
}

// ---------------------------------------------------------------------------
// Kernel A: ||e_k||^2 (+ half table) per code + zero accumulators
// ---------------------------------------------------------------------------
__global__ void prep_kernel(const float* __restrict__ E) {
    if (blockIdx.x == 0 && threadIdx.x == 0) {
        d_loss_acc = 0.0; d_fb_count = 0; d_ref_count = 0;
    }
    int warp = (blockIdx.x * blockDim.x + threadIdx.x) >> 5;
    int lane = threadIdx.x & 31;
    if (warp < KCODE) {
        const float* row = E + (size_t)warp * CH;
        float s = 0.f;
        #pragma unroll
        for (int d = lane; d < CH; d += 32) { float v = row[d]; s = fmaf(v, v, s); }
        #pragma unroll
        for (int off = 16; off > 0; off >>= 1) s += __shfl_xor_sync(0xFFFFFFFFu, s, off);
        if (lane == 0) { d_enorm[warp] = s; d_enorm05[warp] = 0.5f * s; }
    }
}

// ---------------------------------------------------------------------------
// Kernel B: E -> fp16, pre-swizzled chunked blob
// ---------------------------------------------------------------------------
__global__ void eblob_kernel(const float* __restrict__ E) {
    int idx = blockIdx.x * 256 + threadIdx.x;
    int k  = idx >> 6;
    int d0 = (idx & 63) * 4;
    const float4 v = *(const float4*)(E + (size_t)k * CH + d0);
    __half h[4];
    h[0] = __float2half_rn(v.x); h[1] = __float2half_rn(v.y);
    h[2] = __float2half_rn(v.z); h[3] = __float2half_rn(v.w);
    int ct = k >> 7, row = k & 127, kc = d0 >> 6, col = d0 & 63;
    size_t chunk = ((size_t)(ct * N_CHUNKS + kc)) * STAGE_BYTES;
    uint32_t off = SWZ128((uint32_t)(row * 128 + col * 2));
    *(uint2*)(d_eblob + chunk + off) = *(uint2*)h;
}

// ---------------------------------------------------------------------------
// Kernel C: 1-term fp16 GEMM, A fragments register-resident across all tiles.
// SMEM: A stage [4x16KB]=64KB | B[6 x 16KB]=96KB -> 160KB
// ---------------------------------------------------------------------------
#define SM_A   0
#define SM_B   65536
#define SM_TOTAL 163840

__global__ __launch_bounds__(256, 1)
void vq_mma_kernel(const float* __restrict__ X) {
    extern __shared__ char smem[];
    const uint32_t sb = smem_u32(smem);
    const int tid  = threadIdx.x;
    const int lane = tid & 31;
    const int wid  = tid >> 5;
    const int warpM = wid >> 1;
    const int warpN = wid & 1;
    const int n0 = blockIdx.x * M_TILE;
    const int b  = n0 >> 10;
    const int r0 = n0 & 1023;
    const float* Xb = X + (size_t)b * (CH * HH * WW) + r0;

    auto copy_stage = [&](int it) {
        uint32_t dst = sb + SM_B + (uint32_t)(it % N_STAGES) * STAGE_BYTES + tid * 16u;
        const uint8_t* src = d_eblob + (size_t)it * STAGE_BYTES + tid * 16;
        #pragma unroll
        for (int p = 0; p < 4; p++) cpasync16(dst + p * 4096u, src + p * 4096);
        asm volatile("cp.async.commit_group;" ::: "memory");
    };
    copy_stage(0); copy_stage(1); copy_stage(2); copy_stage(3);

    // ---- A prologue: stage X (fp16, swizzled), then hoist ALL A frags ----
    #pragma unroll
    for (int l = 0; l < M_TILE * CH / 256; l++) {
        int i = tid + l * 256;
        int d = i >> 7, m = i & 127;
        float v = Xb[(size_t)d * 1024 + m];
        int chunk = d >> 6, c = d & 63;
        uint32_t off = SWZ128((uint32_t)(m * 128 + c * 2));
        *(__half*)(smem + SM_A + chunk * CHUNK_BYTES + off) = __float2half_rn(v);
    }
    __syncthreads();

    const uint32_t a_row = (uint32_t)(warpM * 32 + (lane & 15)) * 128;
    const uint32_t a_col = (uint32_t)(lane >> 4) * 16;
    const uint32_t b_row = (uint32_t)(warpN * 64 + (lane & 7) + ((lane >> 4) * 8)) * 128;
    const uint32_t b_col = (uint32_t)((lane >> 3) & 1) * 16;

    uint32_t Areg[N_CHUNKS][4][2][4];   // [kc][ks][mt][reg] — register resident
    #pragma unroll
    for (int kc = 0; kc < N_CHUNKS; kc++)
        #pragma unroll
        for (int ks = 0; ks < 4; ks++)
            #pragma unroll
            for (int mt = 0; mt < 2; mt++)
                ldsm4(Areg[kc][ks][mt],
                      sb + SM_A + (uint32_t)kc * CHUNK_BYTES +
                      SWZ128(a_row + (uint32_t)mt * 2048 + a_col + (uint32_t)ks * 32));

    // per-token-slot top-3 (value-only third)
    float tv1[4], tv2[4], tv3[4]; int ti1[4], ti2[4];
    #pragma unroll
    for (int t = 0; t < 4; t++) {
        tv1[t] = tv2[t] = tv3[t] = -FLT_MAX;
        ti1[t] = ti2[t] = 0;
    }

    const float2* en2 = (const float2*)d_enorm05;

    for (int ct = 0; ct < N_TILES; ct++) {
        float acc[2][8][4];
        #pragma unroll
        for (int mt = 0; mt < 2; mt++)
            #pragma unroll
            for (int nt = 0; nt < 8; nt++)
                #pragma unroll
                for (int e = 0; e < 4; e++) acc[mt][nt][e] = 0.f;

        #pragma unroll
        for (int kc2 = 0; kc2 < N_CHUNKS; kc2 += 2) {
            int it = ct * N_CHUNKS + kc2;
            asm volatile("cp.async.wait_group 2;" ::: "memory");
            __syncthreads();
            // barrier proves all warps done with stages (it-2),(it-1): the
            // buffers (it+4)%6,(it+5)%6 are those stages' buffers.
            if (it + 4 < TOTAL_ITERS) copy_stage(it + 4);
            if (it + 5 < TOTAL_ITERS) copy_stage(it + 5);

            #pragma unroll
            for (int kk = 0; kk < 2; kk++) {
                const int kc = kc2 + kk;
                const uint32_t bh_base =
                    sb + SM_B + (uint32_t)((it + kk) % N_STAGES) * STAGE_BYTES;
                #pragma unroll
                for (int ks = 0; ks < 4; ks++) {
                    uint32_t bf[4][4];
                    #pragma unroll
                    for (int np = 0; np < 4; np++)
                        ldsm4(bf[np], bh_base +
                              SWZ128(b_row + (uint32_t)np * 2048 + b_col + (uint32_t)ks * 32));
                    #pragma unroll
                    for (int mt = 0; mt < 2; mt++)
                        #pragma unroll
                        for (int nt = 0; nt < 8; nt++)
                            mma16816(acc[mt][nt], Areg[kc][ks][mt],
                                     bf[nt >> 1][(nt & 1) * 2], bf[nt >> 1][(nt & 1) * 2 + 1]);
                }
            }
        }

        // ---- epilogue: v = dot - 0.5||e||^2, top-3 insert ----
        const int cb = ct * N_TILE + warpN * 64;
        #pragma unroll
        for (int mt = 0; mt < 2; mt++)
            #pragma unroll
            for (int nt = 0; nt < 8; nt++) {
                int col0 = cb + nt * 8 + (lane & 3) * 2;
                float2 e = __ldg(en2 + (col0 >> 1));
                #pragma unroll
                for (int half = 0; half < 2; half++) {
                    int t = mt * 2 + half;
                    float v0 = acc[mt][nt][half * 2 + 0] - e.x;
                    float v1 = acc[mt][nt][half * 2 + 1] - e.y;
                    ins3vi(v0, col0,     tv1[t], ti1[t], tv2[t], ti2[t], tv3[t]);
                    ins3vi(v1, col0 + 1, tv1[t], ti1[t], tv2[t], ti2[t], tv3[t]);
                }
            }
    }

    // ---- quad reduction within warp: exact top-3 merge ----
    #pragma unroll
    for (int t = 0; t < 4; t++) {
        #pragma unroll
        for (int m = 1; m <= 2; m <<= 1) {
            float ov1 = __shfl_xor_sync(0xFFFFFFFFu, tv1[t], m);
            float ov2 = __shfl_xor_sync(0xFFFFFFFFu, tv2[t], m);
            float ov3 = __shfl_xor_sync(0xFFFFFFFFu, tv3[t], m);
            int   oi1 = __shfl_xor_sync(0xFFFFFFFFu, ti1[t], m);
            int   oi2 = __shfl_xor_sync(0xFFFFFFFFu, ti2[t], m);
            ins3vi(ov1, oi1, tv1[t], ti1[t], tv2[t], ti2[t], tv3[t]);
            ins3vi(ov2, oi2, tv1[t], ti1[t], tv2[t], ti2[t], tv3[t]);
            if (ov3 > tv3[t]) tv3[t] = ov3;   // value-only third
        }
    }

    // ---- cross-warpN merge via smem (B region dead) ----
    __syncthreads();
    float* rv1 = (float*)(smem + SM_B);
    float* rv2 = (float*)(smem + SM_B + 1024);
    float* rv3 = (float*)(smem + SM_B + 2048);
    int*   ri1 = (int*)  (smem + SM_B + 3072);
    int*   ri2 = (int*)  (smem + SM_B + 4096);
    #pragma unroll
    for (int t = 0; t < 4; t++) {
        if ((lane & 3) == 0) {
            int mt = t >> 1, half = t & 1;
            int tl = warpN * 128 + warpM * 32 + mt * 16 + half * 8 + (lane >> 2);
            rv1[tl] = tv1[t]; rv2[tl] = tv2[t]; rv3[tl] = tv3[t];
            ri1[tl] = ti1[t]; ri2[tl] = ti2[t];
        }
    }
    __syncthreads();
    if (tid < M_TILE) {
        float v1 = rv1[tid], v2 = rv2[tid], v3 = rv3[tid];
        int   i1 = ri1[tid], i2 = ri2[tid];
        ins3vi(rv1[128 + tid], ri1[128 + tid], v1, i1, v2, i2, v3);
        ins3vi(rv2[128 + tid], ri2[128 + tid], v1, i1, v2, i2, v3);
        if (rv3[128 + tid] > v3) v3 = rv3[128 + tid];
        int n = n0 + tid;
        d_idx[n] = i1;
        if (v1 - v3 < WIN2B) {
            int p = atomicAdd(&d_fb_count, 1);
            if (p < NTOK) { d_fb_list[p] = n; d_fb_best[n] = 0xFFFFFFFFFFFFFFFFull; }
        } else if (v1 - v2 < WIN2B) {
            int p = atomicAdd(&d_ref_count, 1);
            if (p < NTOK) { d_ref_n[p] = n; d_ref_i1[p] = i1; d_ref_i2[p] = i2; }
        }
    }
}

// ---------------------------------------------------------------------------
// Kernel D1: exact fp32 refine of 2 candidate codes. One warp per token.
// ---------------------------------------------------------------------------
__global__ __launch_bounds__(256)
void refine_kernel(const float* __restrict__ X, const float* __restrict__ E) {
    const int lane = threadIdx.x & 31;
    const int gw = blockIdx.x * 8 + (threadIdx.x >> 5);
    int cnt = d_ref_count; if (cnt > NTOK) cnt = NTOK;
    for (int w = gw; w < cnt; w += gridDim.x * 8) {
        int n = d_ref_n[w], i1 = d_ref_i1[w], i2 = d_ref_i2[w];
        int b = n >> 10, r = n & 1023;
        const float* Xp = X + (size_t)b * (CH * HH * WW) + r;
        const float* e1 = E + (size_t)i1 * CH;
        const float* e2 = E + (size_t)i2 * CH;
        float s1 = 0.f, s2 = 0.f;
        #pragma unroll
        for (int j = 0; j < CH / 32; j++) {
            int d = lane + j * 32;
            float x = Xp[(size_t)d * 1024];
            s1 = fmaf(x, e1[d], s1);
            s2 = fmaf(x, e2[d], s2);
        }
        #pragma unroll
        for (int o = 16; o > 0; o >>= 1) {
            s1 += __shfl_xor_sync(0xFFFFFFFFu, s1, o);
            s2 += __shfl_xor_sync(0xFFFFFFFFu, s2, o);
        }
        if (lane == 0) {
            float sc1 = fmaf(-2.f, s1, d_enorm[i1]);
            float sc2 = fmaf(-2.f, s2, d_enorm[i2]);
            int win = (sc2 < sc1 || (sc2 == sc1 && i2 < i1)) ? i2 : i1;
            d_idx[n] = win;
        }
    }
}

// ---------------------------------------------------------------------------
// Kernel D2: full exact fp32 rescan (rare), mini-GEMM tiles.
// ---------------------------------------------------------------------------
__global__ __launch_bounds__(128)
void fb_kernel(const float* __restrict__ X, const float* __restrict__ E) {
    __shared__ float xs[FBT][CH];
    __shared__ unsigned long long red[FBT][128];
    const int tid = threadIdx.x;
    int cnt = d_fb_count; if (cnt > NTOK) cnt = NTOK;
    const int ngrp = (cnt + FBT - 1) / FBT;
    const int items = ngrp * (KCODE / 128);
    for (int w = blockIdx.x; w < items; w += gridDim.x) {
        const int grp = w >> 6, seg = w & 63;
        __syncthreads();
        for (int i = tid; i < FBT * CH; i += 128) {
            int t = i >> 8, d = i & 255;
            int li = grp * FBT + t;
            int n = d_fb_list[li < cnt ? li : 0];
            int b = n >> 10, r = n & 1023;
            xs[t][d] = X[(size_t)b * (CH * HH * WW) + (size_t)d * 1024 + r];
        }
        __syncthreads();
        const int c = seg * 128 + tid;
        const float4* e4 = (const float4*)(E + (size_t)c * CH);
        float dots[FBT];
        #pragma unroll
        for (int t = 0; t < FBT; t++) dots[t] = 0.f;
        #pragma unroll 4
        for (int q = 0; q < CH / 4; q++) {
            float4 e = e4[q];
            #pragma unroll
            for (int t = 0; t < FBT; t++) {
                float4 a = *(const float4*)&xs[t][q * 4];
                dots[t] = fmaf(a.x, e.x, fmaf(a.y, e.y, fmaf(a.z, e.z, fmaf(a.w, e.w, dots[t]))));
            }
        }
        float en = d_enorm[c];
        #pragma unroll
        for (int t = 0; t < FBT; t++) {
            float sc = fmaf(-2.f, dots[t], en);
            red[t][tid] = ((unsigned long long)ord_f32(sc) << 32) | (unsigned)c;
        }
        __syncthreads();
        {
            int t = tid >> 3, l8 = tid & 7;
            unsigned long long m = 0xFFFFFFFFFFFFFFFFull;
            #pragma unroll
            for (int j = 0; j < 16; j++) {
                unsigned long long v = red[t][l8 + j * 8];
                if (v < m) m = v;
            }
            #pragma unroll
            for (int o = 4; o > 0; o >>= 1) {
                unsigned long long v = __shfl_xor_sync(0xFFFFFFFFu, m, o);
                if (v < m) m = v;
            }
            int li = grp * FBT + t;
            if (l8 == 0 && li < cnt) atomicMin(&d_fb_best[d_fb_list[li]], m);
        }
    }
}

__global__ void fb_finalize_kernel() {
    int w = blockIdx.x * 256 + threadIdx.x;
    int cnt = d_fb_count; if (cnt > NTOK) cnt = NTOK;
    if (w < cnt) {
        int n = d_fb_list[w];
        d_idx[n] = (int)(unsigned)(d_fb_best[n] & 0xFFFFFFFFull);
    }
}

// ---------------------------------------------------------------------------
// Kernel E: gather (coalesced via smem staging) + loss. Block = 32 tokens.
// ---------------------------------------------------------------------------
__global__ __launch_bounds__(256)
void gather_loss_kernel(const float* __restrict__ X,
                        const float* __restrict__ E,
                        float* __restrict__ out) {
    __shared__ float es[32][257];       // padded: bank-conflict-free
    __shared__ float sred[256];
    const int tid = threadIdx.x;
    const int n0 = blockIdx.x * 32;
    const int b  = n0 >> 10;
    const int r0 = n0 & 1023;

    // stage 32 codebook rows, coalesced (row-contiguous reads)
    #pragma unroll 4
    for (int p = 0; p < 32; p++) {
        int k = d_idx[n0 + p];
        es[p][tid] = E[(size_t)k * CH + tid];
    }
    if (tid < 32) out[IDX_OFF + n0 + tid] = (float)d_idx[n0 + tid];
    __syncthreads();

    const int t = tid & 31;             // token within group
    const int cg = tid >> 5;            // c-group 0..7
    float acc = 0.f;
    #pragma unroll 8
    for (int p = 0; p < 32; p++) {
        int c = cg + p * 8;
        size_t i = (size_t)b * (CH * HH * WW) + (size_t)c * 1024 + r0 + t;
        float q = es[t][c];
        float x = X[i];
        out[i] = q;
        float d = q - x;
        acc = fmaf(d, d, acc);
    }
    sred[tid] = acc;
    __syncthreads();
    #pragma unroll
    for (int s = 128; s > 0; s >>= 1) {
        if (tid < s) sred[tid] += sred[tid + s];
        __syncthreads();
    }
    if (tid == 0) atomicAdd(&d_loss_acc, (double)sred[0]);
}

__global__ void finalize_kernel(float* __restrict__ out) {
    out[LOSS_OFF] = (float)(d_loss_acc * 1.25 / (double)QUANT_ELEMS);
}

// ---------------------------------------------------------------------------
extern "C" void kernel_launch(void* const* d_in, const int* in_sizes, int n_in,
                              void* d_out, int out_size) {
    const float* X = (const float*)d_in[0];
    const float* E = (const float*)d_in[1];
    float* out = (float*)d_out;

    cudaFuncSetAttribute(vq_mma_kernel, cudaFuncAttributeMaxDynamicSharedMemorySize, SM_TOTAL);

    prep_kernel<<<KCODE / 8, 256>>>(E);
    eblob_kernel<<<KCODE * CH / 4 / 256, 256>>>(E);
    vq_mma_kernel<<<NTOK / M_TILE, 256, SM_TOTAL>>>(X);
    refine_kernel<<<128, 256>>>(X, E);
    fb_kernel<<<256, 128>>>(X, E);
    fb_finalize_kernel<<<NTOK / 256, 256>>>();
    gather_loss_kernel<<<NTOK / 32, 256>>>(X, E, out);
    finalize_kernel<<<1, 1>>>(out);
}

// round 10
// speedup vs baseline: 7.3170x; 1.0167x over previous
#include <cuda_runtime.h>
#include <cuda_fp16.h>
#include <float.h>
#include <stdint.h>

// ---------------------------------------------------------------------------
// Problem constants
// ---------------------------------------------------------------------------
#define BATCH 16
#define CH    256
#define HH    32
#define WW    32
#define NTOK  (BATCH*HH*WW)           // 16384
#define KCODE 8192
#define QUANT_ELEMS (BATCH*CH*HH*WW)  // 4194304
#define LOSS_OFF  QUANT_ELEMS
#define IDX_OFF   (QUANT_ELEMS + 1)

#define M_TILE 128
#define N_TILE 128
#define N_TILES (KCODE / N_TILE)      // 64
#define KC 64
#define N_CHUNKS (CH / KC)            // 4
#define CHUNK_BYTES 16384             // 128 rows x 128B
#define STAGE_BYTES 16384
#define N_STAGES 6
#define TOTAL_ITERS (N_TILES * N_CHUNKS)  // 256

// 2*B, B = 12-sigma bound on 1-term fp16 v-score error (std ~6.3e-3)
#define WIN2B 0.15f

#define FBT 16

// ---------------------------------------------------------------------------
// Device scratch (allocation-free)
// ---------------------------------------------------------------------------
__device__ __align__(128) uint8_t d_eblob[(size_t)TOTAL_ITERS * STAGE_BYTES]; // 4 MB
__device__ float  d_enorm[KCODE];
__device__ float  d_enorm05[KCODE];
__device__ int    d_idx[NTOK];
__device__ float  d_dist[NTOK];       // per-token ||e_k - x||^2 - ||x||^2 (= score)
__device__ int    d_ref_count;
__device__ int    d_ref_n[NTOK];
__device__ int    d_ref_i1[NTOK];
__device__ int    d_ref_i2[NTOK];
__device__ int    d_fb_count;
__device__ int    d_fb_list[NTOK];
__device__ unsigned long long d_fb_best[NTOK];
__device__ double d_loss_acc;         // accumulates Sum||x||^2 + Sum score

// ---------------------------------------------------------------------------
// Helpers
// ---------------------------------------------------------------------------
__device__ __forceinline__ uint32_t smem_u32(const void* p) {
    uint32_t a;
    asm("{ .reg .u64 t; cvta.to.shared.u64 t, %1; cvt.u32.u64 %0, t; }" : "=r"(a) : "l"(p));
    return a;
}
#define SWZ128(off) ((off) ^ (((off) >> 3) & 0x70))

__device__ __forceinline__ void ldsm4(uint32_t* r, uint32_t addr) {
    asm volatile("ldmatrix.sync.aligned.m8n8.x4.shared.b16 {%0,%1,%2,%3}, [%4];"
                 : "=r"(r[0]), "=r"(r[1]), "=r"(r[2]), "=r"(r[3]) : "r"(addr));
}

__device__ __forceinline__ void mma16816(float* d, const uint32_t* a,
                                         uint32_t b0, uint32_t b1) {
    asm volatile(
        "mma.sync.aligned.m16n8k16.row.col.f32.f16.f16.f32 "
        "{%0,%1,%2,%3}, {%4,%5,%6,%7}, {%8,%9}, {%0,%1,%2,%3};"
        : "+f"(d[0]), "+f"(d[1]), "+f"(d[2]), "+f"(d[3])
        : "r"(a[0]), "r"(a[1]), "r"(a[2]), "r"(a[3]), "r"(b0), "r"(b1));
}

__device__ __forceinline__ void cpasync16(uint32_t dst, const void* src) {
    asm volatile("cp.async.cg.shared.global [%0], [%1], 16;" :: "r"(dst), "l"(src));
}

__device__ __forceinline__ unsigned ord_f32(float f) {
    unsigned u = __float_as_uint(f);
    return (u & 0x80000000u) ? ~u : (u | 0x80000000u);
}
__device__ __forceinline__ float ord_inv(unsigned o) {
    unsigned bits = (o & 0x80000000u) ? (o ^ 0x80000000u) : ~o;
    return __uint_as_float(bits);
}

// top-3 insert; third slot value-only (its index can never rank top-2 in a merge)
__device__ __forceinline__ void ins3vi(float v, int i,
                                       float& v1, int& i1,
                                       float& v2, int& i2, float& v3) {
    if (v > v3) {
        if (v > v1)      { v3 = v2; v2 = v1; i2 = i1; v1 = v; i1 = i; }
        else if (v > v2) { v3 = v2; v2 = v;  i2 = i; }
        else             { v3 = v; }
    }
}

// ---------------------------------------------------------------------------
// Kernel A (fused): one warp per code: norm + fp16 convert + swizzled store.
// ---------------------------------------------------------------------------
__global__ void prep_eblob_kernel(const float* __restrict__ E) {
    if (blockIdx.x == 0 && threadIdx.x == 0) {
        d_loss_acc = 0.0; d_fb_count = 0; d_ref_count = 0;
    }
    const int k    = blockIdx.x * 8 + (threadIdx.x >> 5);
    const int lane = threadIdx.x & 31;
    const int d0   = lane * 8;
    const float* row = E + (size_t)k * CH + d0;
    float4 a = *(const float4*)row;
    float4 c = *(const float4*)(row + 4);

    float s = a.x*a.x + a.y*a.y + a.z*a.z + a.w*a.w
            + c.x*c.x + c.y*c.y + c.z*c.z + c.w*c.w;
    #pragma unroll
    for (int o = 16; o > 0; o >>= 1) s += __shfl_xor_sync(0xFFFFFFFFu, s, o);
    if (lane == 0) { d_enorm[k] = s; d_enorm05[k] = 0.5f * s; }

    __half h0[4], h1[4];
    h0[0] = __float2half_rn(a.x); h0[1] = __float2half_rn(a.y);
    h0[2] = __float2half_rn(a.z); h0[3] = __float2half_rn(a.w);
    h1[0] = __float2half_rn(c.x); h1[1] = __float2half_rn(c.y);
    h1[2] = __float2half_rn(c.z); h1[3] = __float2half_rn(c.w);

    int ct = k >> 7, rw = k & 127, kc = d0 >> 6, col = d0 & 63;
    size_t chunk = ((size_t)(ct * N_CHUNKS + kc)) * STAGE_BYTES;
    *(uint2*)(d_eblob + chunk + SWZ128((uint32_t)(rw * 128 + col * 2)))     = *(uint2*)h0;
    *(uint2*)(d_eblob + chunk + SWZ128((uint32_t)(rw * 128 + col * 2 + 8))) = *(uint2*)h1;
}

// ---------------------------------------------------------------------------
// Kernel C: 1-term fp16 GEMM, A register-resident; also computes Sum||x||^2
// and per-token coarse score d_dist = -2*v1.
// SMEM: A stage [4x16KB]=64KB | B[6 x 16KB]=96KB -> 160KB dynamic (+1KB static)
// ---------------------------------------------------------------------------
#define SM_A   0
#define SM_B   65536
#define SM_TOTAL 163840

__global__ __launch_bounds__(256, 1)
void vq_mma_kernel(const float* __restrict__ X) {
    extern __shared__ char smem[];
    __shared__ float x2p[256];
    const uint32_t sb = smem_u32(smem);
    const int tid  = threadIdx.x;
    const int lane = tid & 31;
    const int wid  = tid >> 5;
    const int warpM = wid >> 1;
    const int warpN = wid & 1;
    const int n0 = blockIdx.x * M_TILE;
    const int b  = n0 >> 10;
    const int r0 = n0 & 1023;
    const float* Xb = X + (size_t)b * (CH * HH * WW) + r0;

    auto copy_stage = [&](int it) {
        uint32_t dst = sb + SM_B + (uint32_t)(it % N_STAGES) * STAGE_BYTES + tid * 16u;
        const uint8_t* src = d_eblob + (size_t)it * STAGE_BYTES + tid * 16;
        #pragma unroll
        for (int p = 0; p < 4; p++) cpasync16(dst + p * 4096u, src + p * 4096);
        asm volatile("cp.async.commit_group;" ::: "memory");
    };
    copy_stage(0); copy_stage(1); copy_stage(2); copy_stage(3);

    // ---- A prologue: stage X (fp16, swizzled); accumulate exact Sum x^2 ----
    float x2 = 0.f;
    #pragma unroll
    for (int l = 0; l < M_TILE * CH / 256; l++) {
        int i = tid + l * 256;
        int d = i >> 7, m = i & 127;
        float v = Xb[(size_t)d * 1024 + m];
        x2 = fmaf(v, v, x2);
        int chunk = d >> 6, c = d & 63;
        uint32_t off = SWZ128((uint32_t)(m * 128 + c * 2));
        *(__half*)(smem + SM_A + chunk * CHUNK_BYTES + off) = __float2half_rn(v);
    }
    x2p[tid] = x2;
    __syncthreads();
    if (tid < 128) x2p[tid] += x2p[tid + 128];
    __syncthreads();
    if (tid < 64) x2p[tid] += x2p[tid + 64];
    __syncthreads();
    if (tid < 32) {
        float s = x2p[tid] + x2p[tid + 32];
        #pragma unroll
        for (int o = 16; o > 0; o >>= 1) s += __shfl_xor_sync(0xFFFFFFFFu, s, o);
        if (tid == 0) atomicAdd(&d_loss_acc, (double)s);
    }

    const uint32_t a_row = (uint32_t)(warpM * 32 + (lane & 15)) * 128;
    const uint32_t a_col = (uint32_t)(lane >> 4) * 16;
    const uint32_t b_row = (uint32_t)(warpN * 64 + (lane & 7) + ((lane >> 4) * 8)) * 128;
    const uint32_t b_col = (uint32_t)((lane >> 3) & 1) * 16;

    uint32_t Areg[N_CHUNKS][4][2][4];   // [kc][ks][mt][reg]
    #pragma unroll
    for (int kc = 0; kc < N_CHUNKS; kc++)
        #pragma unroll
        for (int ks = 0; ks < 4; ks++)
            #pragma unroll
            for (int mt = 0; mt < 2; mt++)
                ldsm4(Areg[kc][ks][mt],
                      sb + SM_A + (uint32_t)kc * CHUNK_BYTES +
                      SWZ128(a_row + (uint32_t)mt * 2048 + a_col + (uint32_t)ks * 32));

    float tv1[4], tv2[4], tv3[4]; int ti1[4], ti2[4];
    #pragma unroll
    for (int t = 0; t < 4; t++) {
        tv1[t] = tv2[t] = tv3[t] = -FLT_MAX;
        ti1[t] = ti2[t] = 0;
    }

    const float2* en2 = (const float2*)d_enorm05;

    for (int ct = 0; ct < N_TILES; ct++) {
        float acc[2][8][4];
        #pragma unroll
        for (int mt = 0; mt < 2; mt++)
            #pragma unroll
            for (int nt = 0; nt < 8; nt++)
                #pragma unroll
                for (int e = 0; e < 4; e++) acc[mt][nt][e] = 0.f;

        #pragma unroll
        for (int kc2 = 0; kc2 < N_CHUNKS; kc2 += 2) {
            int it = ct * N_CHUNKS + kc2;
            asm volatile("cp.async.wait_group 2;" ::: "memory");
            __syncthreads();
            if (it + 4 < TOTAL_ITERS) copy_stage(it + 4);
            if (it + 5 < TOTAL_ITERS) copy_stage(it + 5);

            #pragma unroll
            for (int kk = 0; kk < 2; kk++) {
                const int kc = kc2 + kk;
                const uint32_t bh_base =
                    sb + SM_B + (uint32_t)((it + kk) % N_STAGES) * STAGE_BYTES;
                #pragma unroll
                for (int ks = 0; ks < 4; ks++) {
                    uint32_t bf[4][4];
                    #pragma unroll
                    for (int np = 0; np < 4; np++)
                        ldsm4(bf[np], bh_base +
                              SWZ128(b_row + (uint32_t)np * 2048 + b_col + (uint32_t)ks * 32));
                    #pragma unroll
                    for (int mt = 0; mt < 2; mt++)
                        #pragma unroll
                        for (int nt = 0; nt < 8; nt++)
                            mma16816(acc[mt][nt], Areg[kc][ks][mt],
                                     bf[nt >> 1][(nt & 1) * 2], bf[nt >> 1][(nt & 1) * 2 + 1]);
                }
            }
        }

        const int cb = ct * N_TILE + warpN * 64;
        #pragma unroll
        for (int mt = 0; mt < 2; mt++)
            #pragma unroll
            for (int nt = 0; nt < 8; nt++) {
                int col0 = cb + nt * 8 + (lane & 3) * 2;
                float2 e = __ldg(en2 + (col0 >> 1));
                #pragma unroll
                for (int half = 0; half < 2; half++) {
                    int t = mt * 2 + half;
                    float v0 = acc[mt][nt][half * 2 + 0] - e.x;
                    float v1 = acc[mt][nt][half * 2 + 1] - e.y;
                    ins3vi(v0, col0,     tv1[t], ti1[t], tv2[t], ti2[t], tv3[t]);
                    ins3vi(v1, col0 + 1, tv1[t], ti1[t], tv2[t], ti2[t], tv3[t]);
                }
            }
    }

    #pragma unroll
    for (int t = 0; t < 4; t++) {
        #pragma unroll
        for (int m = 1; m <= 2; m <<= 1) {
            float ov1 = __shfl_xor_sync(0xFFFFFFFFu, tv1[t], m);
            float ov2 = __shfl_xor_sync(0xFFFFFFFFu, tv2[t], m);
            float ov3 = __shfl_xor_sync(0xFFFFFFFFu, tv3[t], m);
            int   oi1 = __shfl_xor_sync(0xFFFFFFFFu, ti1[t], m);
            int   oi2 = __shfl_xor_sync(0xFFFFFFFFu, ti2[t], m);
            ins3vi(ov1, oi1, tv1[t], ti1[t], tv2[t], ti2[t], tv3[t]);
            ins3vi(ov2, oi2, tv1[t], ti1[t], tv2[t], ti2[t], tv3[t]);
            if (ov3 > tv3[t]) tv3[t] = ov3;
        }
    }

    __syncthreads();
    float* rv1 = (float*)(smem + SM_B);
    float* rv2 = (float*)(smem + SM_B + 1024);
    float* rv3 = (float*)(smem + SM_B + 2048);
    int*   ri1 = (int*)  (smem + SM_B + 3072);
    int*   ri2 = (int*)  (smem + SM_B + 4096);
    #pragma unroll
    for (int t = 0; t < 4; t++) {
        if ((lane & 3) == 0) {
            int mt = t >> 1, half = t & 1;
            int tl = warpN * 128 + warpM * 32 + mt * 16 + half * 8 + (lane >> 2);
            rv1[tl] = tv1[t]; rv2[tl] = tv2[t]; rv3[tl] = tv3[t];
            ri1[tl] = ti1[t]; ri2[tl] = ti2[t];
        }
    }
    __syncthreads();
    if (tid < M_TILE) {
        float v1 = rv1[tid], v2 = rv2[tid], v3 = rv3[tid];
        int   i1 = ri1[tid], i2 = ri2[tid];
        ins3vi(rv1[128 + tid], ri1[128 + tid], v1, i1, v2, i2, v3);
        ins3vi(rv2[128 + tid], ri2[128 + tid], v1, i1, v2, i2, v3);
        if (rv3[128 + tid] > v3) v3 = rv3[128 + tid];
        int n = n0 + tid;
        d_idx[n]  = i1;
        d_dist[n] = -2.f * v1;     // coarse score; overwritten by refine/fb if listed
        if (v1 - v3 < WIN2B) {
            int p = atomicAdd(&d_fb_count, 1);
            if (p < NTOK) { d_fb_list[p] = n; d_fb_best[n] = 0xFFFFFFFFFFFFFFFFull; }
        } else if (v1 - v2 < WIN2B) {
            int p = atomicAdd(&d_ref_count, 1);
            if (p < NTOK) { d_ref_n[p] = n; d_ref_i1[p] = i1; d_ref_i2[p] = i2; }
        }
    }
}

// ---------------------------------------------------------------------------
// Kernel D1: exact fp32 refine of 2 candidate codes. One warp per token.
// ---------------------------------------------------------------------------
__global__ __launch_bounds__(256)
void refine_kernel(const float* __restrict__ X, const float* __restrict__ E) {
    const int lane = threadIdx.x & 31;
    const int gw = blockIdx.x * 8 + (threadIdx.x >> 5);
    int cnt = d_ref_count; if (cnt > NTOK) cnt = NTOK;
    for (int w = gw; w < cnt; w += gridDim.x * 8) {
        int n = d_ref_n[w], i1 = d_ref_i1[w], i2 = d_ref_i2[w];
        int b = n >> 10, r = n & 1023;
        const float* Xp = X + (size_t)b * (CH * HH * WW) + r;
        const float* e1 = E + (size_t)i1 * CH;
        const float* e2 = E + (size_t)i2 * CH;
        float s1 = 0.f, s2 = 0.f;
        #pragma unroll
        for (int j = 0; j < CH / 32; j++) {
            int d = lane + j * 32;
            float x = Xp[(size_t)d * 1024];
            s1 = fmaf(x, e1[d], s1);
            s2 = fmaf(x, e2[d], s2);
        }
        #pragma unroll
        for (int o = 16; o > 0; o >>= 1) {
            s1 += __shfl_xor_sync(0xFFFFFFFFu, s1, o);
            s2 += __shfl_xor_sync(0xFFFFFFFFu, s2, o);
        }
        if (lane == 0) {
            float sc1 = fmaf(-2.f, s1, d_enorm[i1]);
            float sc2 = fmaf(-2.f, s2, d_enorm[i2]);
            bool two = (sc2 < sc1 || (sc2 == sc1 && i2 < i1));
            d_idx[n]  = two ? i2 : i1;
            d_dist[n] = two ? sc2 : sc1;
        }
    }
}

// ---------------------------------------------------------------------------
// Kernel D2: full exact fp32 rescan (rare), mini-GEMM tiles.
// ---------------------------------------------------------------------------
__global__ __launch_bounds__(128)
void fb_kernel(const float* __restrict__ X, const float* __restrict__ E) {
    __shared__ float xs[FBT][CH];
    __shared__ unsigned long long red[FBT][128];
    const int tid = threadIdx.x;
    int cnt = d_fb_count; if (cnt > NTOK) cnt = NTOK;
    const int ngrp = (cnt + FBT - 1) / FBT;
    const int items = ngrp * (KCODE / 128);
    for (int w = blockIdx.x; w < items; w += gridDim.x) {
        const int grp = w >> 6, seg = w & 63;
        __syncthreads();
        for (int i = tid; i < FBT * CH; i += 128) {
            int t = i >> 8, d = i & 255;
            int li = grp * FBT + t;
            int n = d_fb_list[li < cnt ? li : 0];
            int b = n >> 10, r = n & 1023;
            xs[t][d] = X[(size_t)b * (CH * HH * WW) + (size_t)d * 1024 + r];
        }
        __syncthreads();
        const int c = seg * 128 + tid;
        const float4* e4 = (const float4*)(E + (size_t)c * CH);
        float dots[FBT];
        #pragma unroll
        for (int t = 0; t < FBT; t++) dots[t] = 0.f;
        #pragma unroll 4
        for (int q = 0; q < CH / 4; q++) {
            float4 e = e4[q];
            #pragma unroll
            for (int t = 0; t < FBT; t++) {
                float4 a = *(const float4*)&xs[t][q * 4];
                dots[t] = fmaf(a.x, e.x, fmaf(a.y, e.y, fmaf(a.z, e.z, fmaf(a.w, e.w, dots[t]))));
            }
        }
        float en = d_enorm[c];
        #pragma unroll
        for (int t = 0; t < FBT; t++) {
            float sc = fmaf(-2.f, dots[t], en);
            red[t][tid] = ((unsigned long long)ord_f32(sc) << 32) | (unsigned)c;
        }
        __syncthreads();
        {
            int t = tid >> 3, l8 = tid & 7;
            unsigned long long m = 0xFFFFFFFFFFFFFFFFull;
            #pragma unroll
            for (int j = 0; j < 16; j++) {
                unsigned long long v = red[t][l8 + j * 8];
                if (v < m) m = v;
            }
            #pragma unroll
            for (int o = 4; o > 0; o >>= 1) {
                unsigned long long v = __shfl_xor_sync(0xFFFFFFFFu, m, o);
                if (v < m) m = v;
            }
            int li = grp * FBT + t;
            if (l8 == 0 && li < cnt) atomicMin(&d_fb_best[d_fb_list[li]], m);
        }
    }
}

__global__ void fb_finalize_kernel() {
    int w = blockIdx.x * 256 + threadIdx.x;
    int cnt = d_fb_count; if (cnt > NTOK) cnt = NTOK;
    if (w < cnt) {
        int n = d_fb_list[w];
        unsigned long long key = d_fb_best[n];
        d_idx[n]  = (int)(unsigned)(key & 0xFFFFFFFFull);
        d_dist[n] = ord_inv((unsigned)(key >> 32));
    }
}

// ---------------------------------------------------------------------------
// Kernel E: pure gather (coalesced via smem staging) + score-sum. 32 tok/block.
// ---------------------------------------------------------------------------
__global__ __launch_bounds__(256)
void gather_kernel(const float* __restrict__ E, float* __restrict__ out) {
    __shared__ float es[32][257];
    const int tid = threadIdx.x;
    const int n0 = blockIdx.x * 32;
    const int b  = n0 >> 10;
    const int r0 = n0 & 1023;

    #pragma unroll 4
    for (int p = 0; p < 32; p++) {
        int k = d_idx[n0 + p];
        es[p][tid] = E[(size_t)k * CH + tid];
    }
    if (tid < 32) {
        out[IDX_OFF + n0 + tid] = (float)d_idx[n0 + tid];
        float s = d_dist[n0 + tid];
        #pragma unroll
        for (int o = 16; o > 0; o >>= 1) s += __shfl_xor_sync(0xFFFFFFFFu, s, o);
        if (tid == 0) atomicAdd(&d_loss_acc, (double)s);
    }
    __syncthreads();

    const int t = tid & 31;
    const int cg = tid >> 5;
    #pragma unroll 8
    for (int p = 0; p < 32; p++) {
        int c = cg + p * 8;
        out[(size_t)b * (CH * HH * WW) + (size_t)c * 1024 + r0 + t] = es[t][c];
    }
}

__global__ void finalize_kernel(float* __restrict__ out) {
    out[LOSS_OFF] = (float)(d_loss_acc * 1.25 / (double)QUANT_ELEMS);
}

// ---------------------------------------------------------------------------
extern "C" void kernel_launch(void* const* d_in, const int* in_sizes, int n_in,
                              void* d_out, int out_size) {
    const float* X = (const float*)d_in[0];
    const float* E = (const float*)d_in[1];
    float* out = (float*)d_out;

    cudaFuncSetAttribute(vq_mma_kernel, cudaFuncAttributeMaxDynamicSharedMemorySize, SM_TOTAL);

    prep_eblob_kernel<<<KCODE / 8, 256>>>(E);
    vq_mma_kernel<<<NTOK / M_TILE, 256, SM_TOTAL>>>(X);
    refine_kernel<<<128, 256>>>(X, E);
    fb_kernel<<<256, 128>>>(X, E);
    fb_finalize_kernel<<<NTOK / 256, 256>>>();
    gather_kernel<<<NTOK / 32, 256>>>(E, out);
    finalize_kernel<<<1, 1>>>(out);
}